// round 1
// baseline (speedup 1.0000x reference)
#include <cuda_runtime.h>
#include <math.h>

// ---------------- problem constants (fixed by setup_inputs) ----------------
#define BS     8
#define QLEN   2048
#define NHEAD  8
#define NLVL   4
#define NPTS   4
#define CCH    32
#define DMODEL 256
#define LVTOT  21760    // 128^2 + 64^2 + 32^2 + 16^2

// level tables
__device__ __constant__ int c_H[NLVL]     = {128, 64, 32, 16};
__device__ __constant__ int c_W[NLVL]     = {128, 64, 32, 16};
__device__ __constant__ int c_start[NLVL] = {0, 16384, 20480, 21504};

// ---------------- scratch (device globals; no allocation allowed) ----------
__device__ float g_v   [(size_t)BS * LVTOT * DMODEL];   // projected values, 178 MB
__device__ float g_off [(size_t)BS * QLEN * DMODEL];    // sampling offsets, 16.8 MB
__device__ float g_attn[(size_t)BS * QLEN * 128];       // attn logits, 8.4 MB
__device__ float g_acc [(size_t)BS * QLEN * DMODEL];    // per-head sampled acc, 16.8 MB

// ---------------- classic SGEMM: C = A[MxK] * B[KxN] + bias[N] -------------
// Requires M%128==0, N%128==0, K%8==0 (true for all 4 call sites).
// 256 threads, BM=BN=128, BK=8, 8x8 thread tile, float4 loads.
__global__ __launch_bounds__(256, 2)
void sgemm_bias(const float* __restrict__ A, const float* __restrict__ B,
                const float* __restrict__ bias, float* __restrict__ C,
                int M, int N, int K)
{
    __shared__ float As[8][128];
    __shared__ float Bs[8][128];

    const int tid = threadIdx.x;
    const int tx  = tid & 15;   // 0..15 -> 8 cols each
    const int ty  = tid >> 4;   // 0..15 -> 8 rows each
    const int m0  = blockIdx.y * 128;
    const int n0  = blockIdx.x * 128;

    // global load mapping
    const int a_row  = tid >> 1;          // 0..127
    const int a_kseg = (tid & 1) << 2;    // 0 or 4
    const int b_row  = tid >> 5;          // 0..7
    const int b_col  = (tid & 31) << 2;   // 0..124

    const float* Aptr = A + (size_t)(m0 + a_row) * K + a_kseg;
    const float* Bptr = B + (size_t)b_row * N + n0 + b_col;

    float acc[8][8];
#pragma unroll
    for (int i = 0; i < 8; i++)
#pragma unroll
        for (int j = 0; j < 8; j++) acc[i][j] = 0.f;

    for (int k0 = 0; k0 < K; k0 += 8) {
        float4 av = *(const float4*)(Aptr + k0);
        float4 bv = *(const float4*)(Bptr + (size_t)k0 * N);
        As[a_kseg + 0][a_row] = av.x;
        As[a_kseg + 1][a_row] = av.y;
        As[a_kseg + 2][a_row] = av.z;
        As[a_kseg + 3][a_row] = av.w;
        *(float4*)&Bs[b_row][b_col] = bv;
        __syncthreads();

#pragma unroll
        for (int k = 0; k < 8; k++) {
            float ar[8], br[8];
            *(float4*)&ar[0] = *(const float4*)&As[k][ty * 8];
            *(float4*)&ar[4] = *(const float4*)&As[k][ty * 8 + 4];
            *(float4*)&br[0] = *(const float4*)&Bs[k][tx * 8];
            *(float4*)&br[4] = *(const float4*)&Bs[k][tx * 8 + 4];
#pragma unroll
            for (int i = 0; i < 8; i++)
#pragma unroll
                for (int j = 0; j < 8; j++)
                    acc[i][j] = fmaf(ar[i], br[j], acc[i][j]);
        }
        __syncthreads();
    }

    float bi[8];
#pragma unroll
    for (int j = 0; j < 8; j++) bi[j] = bias[n0 + tx * 8 + j];

#pragma unroll
    for (int i = 0; i < 8; i++) {
        float* crow = C + (size_t)(m0 + ty * 8 + i) * N + n0 + tx * 8;
        float4 v0, v1;
        v0.x = acc[i][0] + bi[0]; v0.y = acc[i][1] + bi[1];
        v0.z = acc[i][2] + bi[2]; v0.w = acc[i][3] + bi[3];
        v1.x = acc[i][4] + bi[4]; v1.y = acc[i][5] + bi[5];
        v1.z = acc[i][6] + bi[6]; v1.w = acc[i][7] + bi[7];
        *(float4*)(crow)     = v0;
        *(float4*)(crow + 4) = v1;
    }
}

// ---------------- fused softmax + bilinear multi-scale sampling ------------
// One block per (b, q) = 256 threads. Warp w = head h, lane = channel c.
// Every tap read is a coalesced 128B line of g_v.
__global__ __launch_bounds__(256, 8)
void msda_sample(const float* __restrict__ refer_bbox)
{
    const int bq   = blockIdx.x;          // 0 .. BS*QLEN-1
    const int b    = bq >> 11;            // / 2048
    const int h    = threadIdx.x >> 5;
    const int lane = threadIdx.x & 31;

    // --- softmax over 16 logits for this head (redundant per lane, L1 hits)
    const float* la = g_attn + (size_t)bq * 128 + h * 16;
    float lg[16];
    float mx = -1e30f;
#pragma unroll
    for (int j = 0; j < 16; j++) { lg[j] = la[j]; mx = fmaxf(mx, lg[j]); }
    float s = 0.f;
#pragma unroll
    for (int j = 0; j < 16; j++) { lg[j] = expf(lg[j] - mx); s += lg[j]; }
    const float inv = 1.f / s;

    const float* offp = g_off + (size_t)bq * DMODEL + h * 32;
    const float* rbp  = refer_bbox + (size_t)bq * (NLVL * 2);

    float acc = 0.f;
#pragma unroll
    for (int lvl = 0; lvl < NLVL; lvl++) {
        const int Hh = c_H[lvl], Ww = c_W[lvl], st = c_start[lvl];
        const float rx = rbp[lvl * 2 + 0];
        const float ry = rbp[lvl * 2 + 1];
        const size_t base = ((size_t)(b * LVTOT + st)) * DMODEL + h * 32 + lane;

#pragma unroll
        for (int p = 0; p < NPTS; p++) {
            const float ox = offp[lvl * 8 + p * 2 + 0];
            const float oy = offp[lvl * 8 + p * 2 + 1];
            // match reference: loc = rb + off/norm ; x = loc*W - 0.5
            const float x = (rx + ox / (float)Ww) * (float)Ww - 0.5f;
            const float y = (ry + oy / (float)Hh) * (float)Hh - 0.5f;
            const float x0f = floorf(x), y0f = floorf(y);
            const float fx = x - x0f, fy = y - y0f;
            const int x0 = (int)x0f, y0 = (int)y0f;
            const int x1 = x0 + 1,   y1 = y0 + 1;

            const bool vx0 = (x0 >= 0) & (x0 < Ww);
            const bool vx1 = (x1 >= 0) & (x1 < Ww);
            const bool vy0 = (y0 >= 0) & (y0 < Hh);
            const bool vy1 = (y1 >= 0) & (y1 < Hh);

            float w00 = (1.f - fx) * (1.f - fy); if (!(vx0 && vy0)) w00 = 0.f;
            float w10 = fx         * (1.f - fy); if (!(vx1 && vy0)) w10 = 0.f;
            float w01 = (1.f - fx) * fy;         if (!(vx0 && vy1)) w01 = 0.f;
            float w11 = fx         * fy;         if (!(vx1 && vy1)) w11 = 0.f;

            const int cx0 = min(max(x0, 0), Ww - 1);
            const int cx1 = min(max(x1, 0), Ww - 1);
            const int cy0 = min(max(y0, 0), Hh - 1);
            const int cy1 = min(max(y1, 0), Hh - 1);

            const float s00 = g_v[base + (size_t)(cy0 * Ww + cx0) * DMODEL];
            const float s10 = g_v[base + (size_t)(cy0 * Ww + cx1) * DMODEL];
            const float s01 = g_v[base + (size_t)(cy1 * Ww + cx0) * DMODEL];
            const float s11 = g_v[base + (size_t)(cy1 * Ww + cx1) * DMODEL];

            const float samp = w00 * s00 + w10 * s10 + w01 * s01 + w11 * s11;
            acc = fmaf(lg[lvl * 4 + p] * inv, samp, acc);
        }
    }
    g_acc[(size_t)bq * DMODEL + h * 32 + lane] = acc;
}

// ---------------- launch -----------------------------------------------
extern "C" void kernel_launch(void* const* d_in, const int* in_sizes, int n_in,
                              void* d_out, int out_size)
{
    const float* query   = (const float*)d_in[0];   // (8,2048,256)
    const float* rbbox   = (const float*)d_in[1];   // (8,2048,4,2)
    const float* value   = (const float*)d_in[2];   // (8,21760,256)
    // d_in[3] = value_shapes (constants, hardcoded)
    const float* W_value = (const float*)d_in[4];
    const float* b_value = (const float*)d_in[5];
    const float* W_off   = (const float*)d_in[6];
    const float* b_off   = (const float*)d_in[7];
    const float* W_attn  = (const float*)d_in[8];
    const float* b_attn  = (const float*)d_in[9];
    const float* W_out   = (const float*)d_in[10];
    const float* b_out   = (const float*)d_in[11];
    float* out = (float*)d_out;

    float *pv, *poff, *pattn, *pacc;
    cudaGetSymbolAddress((void**)&pv,    g_v);
    cudaGetSymbolAddress((void**)&poff,  g_off);
    cudaGetSymbolAddress((void**)&pattn, g_attn);
    cudaGetSymbolAddress((void**)&pacc,  g_acc);

    const int Mv = BS * LVTOT;   // 174080
    const int Mq = BS * QLEN;    // 16384

    // 1) value projection: v = value @ W_value + b_value
    sgemm_bias<<<dim3(DMODEL / 128, Mv / 128), 256>>>(value, W_value, b_value, pv,
                                                      Mv, DMODEL, DMODEL);
    // 2) sampling offsets: off = query @ W_off + b_off
    sgemm_bias<<<dim3(DMODEL / 128, Mq / 128), 256>>>(query, W_off, b_off, poff,
                                                      Mq, DMODEL, DMODEL);
    // 3) attention logits: attn = query @ W_attn + b_attn
    sgemm_bias<<<dim3(128 / 128, Mq / 128), 256>>>(query, W_attn, b_attn, pattn,
                                                   Mq, 128, DMODEL);
    // 4) softmax + multi-scale deformable bilinear sampling
    msda_sample<<<BS * QLEN, 256>>>(rbbox);
    // 5) output projection: out = acc @ W_out + b_out
    sgemm_bias<<<dim3(DMODEL / 128, Mq / 128), 256>>>(pacc, W_out, b_out, out,
                                                      Mq, DMODEL, DMODEL);
}

// round 4
// speedup vs baseline: 1.2481x; 1.2481x over previous
#include <cuda_runtime.h>
#include <cuda_bf16.h>
#include <cstdint>
#include <stdint.h>
#include <math.h>

// ---------------- problem constants (fixed by setup_inputs) ----------------
#define BS     8
#define QLEN   2048
#define NHEAD  8
#define NLVL   4
#define NPTS   4
#define DMODEL 256
#define LVTOT  21760    // 128^2 + 64^2 + 32^2 + 16^2

__device__ __constant__ int c_H[NLVL]     = {128, 64, 32, 16};
__device__ __constant__ int c_W[NLVL]     = {128, 64, 32, 16};
__device__ __constant__ int c_start[NLVL] = {0, 16384, 20480, 21504};

// ---------------- scratch (device globals; no allocation allowed) ----------
__device__ float g_v   [(size_t)BS * LVTOT * DMODEL];   // projected values
__device__ float g_off [(size_t)BS * QLEN * DMODEL];    // sampling offsets
__device__ float g_attn[(size_t)BS * QLEN * 128];       // attn logits
__device__ float g_acc [(size_t)BS * QLEN * DMODEL];    // sampled accumulators

// ---------------- bf16 split helpers ---------------------------------------
__device__ __forceinline__ void cvt2(float x, float y, uint32_t& hi, uint32_t& lo)
{
    __nv_bfloat16 hx = __float2bfloat16(x);
    __nv_bfloat16 hy = __float2bfloat16(y);
    float rx = x - __bfloat162float(hx);
    float ry = y - __bfloat162float(hy);
    __nv_bfloat16 lx = __float2bfloat16(rx);
    __nv_bfloat16 ly = __float2bfloat16(ry);
    hi = (uint32_t)__bfloat16_as_ushort(hx) | ((uint32_t)__bfloat16_as_ushort(hy) << 16);
    lo = (uint32_t)__bfloat16_as_ushort(lx) | ((uint32_t)__bfloat16_as_ushort(ly) << 16);
}

__device__ __forceinline__ void mma_bf16(float* c, const uint32_t* a, const uint32_t* b)
{
    asm volatile(
        "mma.sync.aligned.m16n8k16.row.col.f32.bf16.bf16.f32 "
        "{%0,%1,%2,%3}, {%4,%5,%6,%7}, {%8,%9}, {%0,%1,%2,%3};\n"
        : "+f"(c[0]), "+f"(c[1]), "+f"(c[2]), "+f"(c[3])
        : "r"(a[0]), "r"(a[1]), "r"(a[2]), "r"(a[3]), "r"(b[0]), "r"(b[1]));
}

// ---------------- tensor-core GEMM: C = A[MxK]*B[KxN] + bias[N] ------------
// bf16x3 split precision (hi*hi + hi*lo + lo*hi), fp32 accumulate.
// Requires M%128==0, N%128==0, K%16==0. 256 threads, BM=BN=128, BK=16.
// Warp grid 4x2: each warp 32 rows x 64 cols = 2 m-tiles x 8 n-tiles (m16n8).
__global__ __launch_bounds__(256, 2)
void mma_gemm_bias(const float* __restrict__ A, const float* __restrict__ B,
                   const float* __restrict__ bias, float* __restrict__ C,
                   int M, int N, int K)
{
    // A: [m][k-pair] u32, row stride 12 (pad: (12g+t)%32 conflict-free)
    // B: [n][k-pair] u32, row stride 12
    __shared__ uint32_t As_hi[128 * 12], As_lo[128 * 12];
    __shared__ uint32_t Bs_hi[128 * 12], Bs_lo[128 * 12];

    const int tid  = threadIdx.x;
    const int wid  = tid >> 5, lane = tid & 31;
    const int g    = lane >> 2, t = lane & 3;
    const int warp_m = wid >> 1, warp_n = wid & 1;
    const int m0 = blockIdx.y * 128, n0 = blockIdx.x * 128;

    // global load mapping
    const int a_row  = tid >> 1;           // 0..127
    const int a_kseg = (tid & 1) * 8;      // 0 or 8
    const int b_krow = tid >> 4;           // 0..15
    const int b_ncol = (tid & 15) * 8;     // 0..120

    const float* Ap = A + (size_t)(m0 + a_row) * K + a_kseg;
    const float* Bp = B + (size_t)b_krow * N + n0 + b_ncol;

    float acc[2][8][4];
#pragma unroll
    for (int i = 0; i < 2; i++)
#pragma unroll
        for (int j = 0; j < 8; j++)
#pragma unroll
            for (int r = 0; r < 4; r++) acc[i][j][r] = 0.f;

    // prologue: load first tile
    float4 a0r = *(const float4*)(Ap);
    float4 a1r = *(const float4*)(Ap + 4);
    float4 b0r = *(const float4*)(Bp);
    float4 b1r = *(const float4*)(Bp + 4);

    for (int k0 = 0; k0 < K; k0 += 16) {
        // ---- convert + store staged tile to smem ----
        {
            const int ab = a_row * 12 + (a_kseg >> 1);
            uint32_t h, l;
            cvt2(a0r.x, a0r.y, h, l); As_hi[ab + 0] = h; As_lo[ab + 0] = l;
            cvt2(a0r.z, a0r.w, h, l); As_hi[ab + 1] = h; As_lo[ab + 1] = l;
            cvt2(a1r.x, a1r.y, h, l); As_hi[ab + 2] = h; As_lo[ab + 2] = l;
            cvt2(a1r.z, a1r.w, h, l); As_hi[ab + 3] = h; As_lo[ab + 3] = l;
        }
        {
            __nv_bfloat16* BH = reinterpret_cast<__nv_bfloat16*>(Bs_hi);
            __nv_bfloat16* BL = reinterpret_cast<__nv_bfloat16*>(Bs_lo);
            float vals[8] = {b0r.x, b0r.y, b0r.z, b0r.w, b1r.x, b1r.y, b1r.z, b1r.w};
#pragma unroll
            for (int j = 0; j < 8; j++) {
                __nv_bfloat16 hh = __float2bfloat16(vals[j]);
                float r = vals[j] - __bfloat162float(hh);
                BH[(b_ncol + j) * 24 + b_krow] = hh;
                BL[(b_ncol + j) * 24 + b_krow] = __float2bfloat16(r);
            }
        }
        __syncthreads();

        // ---- prefetch next tile (hidden behind mma phase) ----
        if (k0 + 16 < K) {
            a0r = *(const float4*)(Ap + k0 + 16);
            a1r = *(const float4*)(Ap + k0 + 20);
            b0r = *(const float4*)(Bp + (size_t)(k0 + 16) * N);
            b1r = *(const float4*)(Bp + (size_t)(k0 + 16) * N + 4);
        }

        // ---- compute ----
        uint32_t ah[2][4], al[2][4];
#pragma unroll
        for (int mt = 0; mt < 2; mt++) {
            const int ar = warp_m * 32 + mt * 16;
            ah[mt][0] = As_hi[(ar + g)     * 12 + t];
            ah[mt][1] = As_hi[(ar + 8 + g) * 12 + t];
            ah[mt][2] = As_hi[(ar + g)     * 12 + t + 4];
            ah[mt][3] = As_hi[(ar + 8 + g) * 12 + t + 4];
            al[mt][0] = As_lo[(ar + g)     * 12 + t];
            al[mt][1] = As_lo[(ar + 8 + g) * 12 + t];
            al[mt][2] = As_lo[(ar + g)     * 12 + t + 4];
            al[mt][3] = As_lo[(ar + 8 + g) * 12 + t + 4];
        }
#pragma unroll
        for (int nt = 0; nt < 8; nt++) {
            const int bc = warp_n * 64 + nt * 8 + g;
            uint32_t bh2[2] = {Bs_hi[bc * 12 + t], Bs_hi[bc * 12 + t + 4]};
            uint32_t bl2[2] = {Bs_lo[bc * 12 + t], Bs_lo[bc * 12 + t + 4]};
#pragma unroll
            for (int mt = 0; mt < 2; mt++) {
                mma_bf16(acc[mt][nt], ah[mt], bh2);
                mma_bf16(acc[mt][nt], ah[mt], bl2);
                mma_bf16(acc[mt][nt], al[mt], bh2);
            }
        }
        __syncthreads();
    }

    // ---- epilogue ----
#pragma unroll
    for (int mt = 0; mt < 2; mt++) {
#pragma unroll
        for (int nt = 0; nt < 8; nt++) {
            const int row = m0 + warp_m * 32 + mt * 16 + g;
            const int col = n0 + warp_n * 64 + nt * 8 + 2 * t;
            float2 bi = *(const float2*)&bias[col];
            float2 r0 = make_float2(acc[mt][nt][0] + bi.x, acc[mt][nt][1] + bi.y);
            float2 r1 = make_float2(acc[mt][nt][2] + bi.x, acc[mt][nt][3] + bi.y);
            *(float2*)&C[(size_t)row * N + col]       = r0;
            *(float2*)&C[(size_t)(row + 8) * N + col] = r1;
        }
    }
}

// ---------------- fused softmax + bilinear multi-scale sampling ------------
// One block per (b,q). Phase A: 128 threads, one per (h,lvl,p): softmax via
// 16-lane shuffle reduce + coordinate/weight/index computation, staged in smem.
// Phase B: warp = head, lane = channel: pure gather + fma.
__global__ __launch_bounds__(256, 8)
void msda_sample(const float* __restrict__ refer_bbox)
{
    __shared__ int   s_idx[128][4];
    __shared__ float s_w[128][4];

    const int bq  = blockIdx.x;
    const int b   = bq >> 11;
    const int tid = threadIdx.x;

    if (tid < 128) {
        const int h   = tid >> 4;
        const int sub = tid & 15;
        const int lvl = sub >> 2;
        const int p   = sub & 3;

        // softmax over this head's 16 logits (16-lane subgroup reduce)
        float logit = g_attn[(size_t)bq * 128 + h * 16 + sub];
        float mx = logit;
#pragma unroll
        for (int o = 8; o >= 1; o >>= 1)
            mx = fmaxf(mx, __shfl_xor_sync(0xffffffffu, mx, o));
        float e = expf(logit - mx);
        float sm = e;
#pragma unroll
        for (int o = 8; o >= 1; o >>= 1)
            sm += __shfl_xor_sync(0xffffffffu, sm, o);
        const float aw = e / sm;

        const int Hh = c_H[lvl], Ww = c_W[lvl], st = c_start[lvl];
        const float rx = refer_bbox[(size_t)bq * 8 + lvl * 2 + 0];
        const float ry = refer_bbox[(size_t)bq * 8 + lvl * 2 + 1];
        const float ox = g_off[(size_t)bq * DMODEL + h * 32 + lvl * 8 + p * 2 + 0];
        const float oy = g_off[(size_t)bq * DMODEL + h * 32 + lvl * 8 + p * 2 + 1];

        const float x = (rx + ox / (float)Ww) * (float)Ww - 0.5f;
        const float y = (ry + oy / (float)Hh) * (float)Hh - 0.5f;
        const float x0f = floorf(x), y0f = floorf(y);
        const float fx = x - x0f, fy = y - y0f;
        const int x0 = (int)x0f, y0 = (int)y0f;
        const int x1 = x0 + 1,   y1 = y0 + 1;

        const bool vx0 = (x0 >= 0) & (x0 < Ww);
        const bool vx1 = (x1 >= 0) & (x1 < Ww);
        const bool vy0 = (y0 >= 0) & (y0 < Hh);
        const bool vy1 = (y1 >= 0) & (y1 < Hh);

        float w00 = (1.f - fx) * (1.f - fy); if (!(vx0 && vy0)) w00 = 0.f;
        float w10 = fx         * (1.f - fy); if (!(vx1 && vy0)) w10 = 0.f;
        float w01 = (1.f - fx) * fy;         if (!(vx0 && vy1)) w01 = 0.f;
        float w11 = fx         * fy;         if (!(vx1 && vy1)) w11 = 0.f;

        const int cx0 = min(max(x0, 0), Ww - 1);
        const int cx1 = min(max(x1, 0), Ww - 1);
        const int cy0 = min(max(y0, 0), Hh - 1);
        const int cy1 = min(max(y1, 0), Hh - 1);

        const int base = (b * LVTOT + st) * DMODEL + h * 32;
        s_idx[tid][0] = base + (cy0 * Ww + cx0) * DMODEL;
        s_idx[tid][1] = base + (cy0 * Ww + cx1) * DMODEL;
        s_idx[tid][2] = base + (cy1 * Ww + cx0) * DMODEL;
        s_idx[tid][3] = base + (cy1 * Ww + cx1) * DMODEL;
        s_w[tid][0] = w00 * aw;
        s_w[tid][1] = w10 * aw;
        s_w[tid][2] = w01 * aw;
        s_w[tid][3] = w11 * aw;
    }
    __syncthreads();

    const int h = tid >> 5, lane = tid & 31;
    float acc = 0.f;
#pragma unroll
    for (int j = 0; j < 16; j++) {
        const int4   id = *(const int4*)  s_idx[h * 16 + j];
        const float4 w  = *(const float4*)s_w  [h * 16 + j];
        acc = fmaf(w.x, g_v[id.x + lane], acc);
        acc = fmaf(w.y, g_v[id.y + lane], acc);
        acc = fmaf(w.z, g_v[id.z + lane], acc);
        acc = fmaf(w.w, g_v[id.w + lane], acc);
    }
    g_acc[(size_t)bq * DMODEL + h * 32 + lane] = acc;
}

// ---------------- launch -----------------------------------------------
extern "C" void kernel_launch(void* const* d_in, const int* in_sizes, int n_in,
                              void* d_out, int out_size)
{
    const float* query   = (const float*)d_in[0];   // (8,2048,256)
    const float* rbbox   = (const float*)d_in[1];   // (8,2048,4,2)
    const float* value   = (const float*)d_in[2];   // (8,21760,256)
    // d_in[3] = value_shapes (hardcoded constants)
    const float* W_value = (const float*)d_in[4];
    const float* b_value = (const float*)d_in[5];
    const float* W_off   = (const float*)d_in[6];
    const float* b_off   = (const float*)d_in[7];
    const float* W_attn  = (const float*)d_in[8];
    const float* b_attn  = (const float*)d_in[9];
    const float* W_out   = (const float*)d_in[10];
    const float* b_out   = (const float*)d_in[11];
    float* out = (float*)d_out;

    float *pv, *poff, *pattn, *pacc;
    cudaGetSymbolAddress((void**)&pv,    g_v);
    cudaGetSymbolAddress((void**)&poff,  g_off);
    cudaGetSymbolAddress((void**)&pattn, g_attn);
    cudaGetSymbolAddress((void**)&pacc,  g_acc);

    const int Mv = BS * LVTOT;   // 174080
    const int Mq = BS * QLEN;    // 16384

    // 1) value projection
    mma_gemm_bias<<<dim3(DMODEL / 128, Mv / 128), 256>>>(value, W_value, b_value, pv,
                                                         Mv, DMODEL, DMODEL);
    // 2) sampling offsets
    mma_gemm_bias<<<dim3(DMODEL / 128, Mq / 128), 256>>>(query, W_off, b_off, poff,
                                                         Mq, DMODEL, DMODEL);
    // 3) attention logits
    mma_gemm_bias<<<dim3(1, Mq / 128), 256>>>(query, W_attn, b_attn, pattn,
                                              Mq, 128, DMODEL);
    // 4) softmax + multi-scale deformable bilinear sampling
    msda_sample<<<BS * QLEN, 256>>>(rbbox);
    // 5) output projection
    mma_gemm_bias<<<dim3(DMODEL / 128, Mq / 128), 256>>>(pacc, W_out, b_out, out,
                                                         Mq, DMODEL, DMODEL);
}

// round 7
// speedup vs baseline: 2.5435x; 2.0378x over previous
#include <cuda_runtime.h>
#include <cuda_bf16.h>
#include <cstdint>
#include <stdint.h>
#include <math.h>

// ---------------- problem constants ----------------------------------------
#define BS     8
#define QLEN   2048
#define NLVL   4
#define DMODEL 256
#define LVTOT  21760    // 128^2+64^2+32^2+16^2

__device__ __constant__ int c_H[NLVL]     = {128, 64, 32, 16};
__device__ __constant__ int c_W[NLVL]     = {128, 64, 32, 16};
__device__ __constant__ int c_start[NLVL] = {0, 16384, 20480, 21504};

// ---------------- scratch (device globals) ----------------------------------
__device__ float g_v   [(size_t)BS * LVTOT * DMODEL];
__device__ float g_off [(size_t)BS * QLEN * DMODEL];
__device__ float g_attn[(size_t)BS * QLEN * 128];
__device__ float g_acc [(size_t)BS * QLEN * DMODEL];

// pre-split, pre-swizzled weight images: [chunk(4)][ntile(N/128)][8192 bf16]
__device__ unsigned short g_Wv_hi[65536], g_Wv_lo[65536];
__device__ unsigned short g_Wo_hi[65536], g_Wo_lo[65536];
__device__ unsigned short g_Wa_hi[32768], g_Wa_lo[32768];
__device__ unsigned short g_Wu_hi[65536], g_Wu_lo[65536];

// ---------------- helpers ----------------------------------------------------
#define SWZ(o) ((o) ^ (((o) >> 3) & 0x70))

__device__ __forceinline__ uint32_t smem_u32(const void* p) {
    return (uint32_t)__cvta_generic_to_shared(p);
}

__device__ __forceinline__ void cp16(uint32_t s, const void* g) {
    asm volatile("cp.async.cg.shared.global [%0], [%1], 16;" :: "r"(s), "l"(g) : "memory");
}
__device__ __forceinline__ void cp_commit() {
    asm volatile("cp.async.commit_group;" ::: "memory");
}
__device__ __forceinline__ void cp_wait(int n) {
    switch (n) {
        case 0:  asm volatile("cp.async.wait_group 0;" ::: "memory"); break;
        case 1:  asm volatile("cp.async.wait_group 1;" ::: "memory"); break;
        case 2:  asm volatile("cp.async.wait_group 2;" ::: "memory"); break;
        default: asm volatile("cp.async.wait_group 3;" ::: "memory"); break;
    }
}

__device__ __forceinline__ void ldsm4(uint32_t* r, uint32_t addr) {
    asm volatile("ldmatrix.sync.aligned.m8n8.x4.shared.b16 {%0,%1,%2,%3}, [%4];"
                 : "=r"(r[0]), "=r"(r[1]), "=r"(r[2]), "=r"(r[3]) : "r"(addr));
}

__device__ __forceinline__ void mma_bf16(float* c, const uint32_t* a, const uint32_t* b)
{
    asm volatile(
        "mma.sync.aligned.m16n8k16.row.col.f32.bf16.bf16.f32 "
        "{%0,%1,%2,%3}, {%4,%5,%6,%7}, {%8,%9}, {%0,%1,%2,%3};\n"
        : "+f"(c[0]), "+f"(c[1]), "+f"(c[2]), "+f"(c[3])
        : "r"(a[0]), "r"(a[1]), "r"(a[2]), "r"(a[3]), "r"(b[0]), "r"(b[1]));
}

__device__ __forceinline__ void cvt2(float x, float y, uint32_t& hi, uint32_t& lo)
{
    __nv_bfloat16 hx = __float2bfloat16(x);
    __nv_bfloat16 hy = __float2bfloat16(y);
    __nv_bfloat16 lx = __float2bfloat16(x - __bfloat162float(hx));
    __nv_bfloat16 ly = __float2bfloat16(y - __bfloat162float(hy));
    hi = (uint32_t)__bfloat16_as_ushort(hx) | ((uint32_t)__bfloat16_as_ushort(hy) << 16);
    lo = (uint32_t)__bfloat16_as_ushort(lx) | ((uint32_t)__bfloat16_as_ushort(ly) << 16);
}

// ---------------- weight prep: split + swizzle into tile images -------------
// W is [K=256][N] row-major. Image block = chunk(4)*(N/128)+ntile, 8192 bf16,
// within block: swizzled (n_in_tile*128 + k_in_chunk*2) byte offsets.
__global__ void prep_w(const float* __restrict__ W, int N,
                       unsigned short* __restrict__ Hi, unsigned short* __restrict__ Lo)
{
    int idx = blockIdx.x * 256 + threadIdx.x;
    if (idx >= 256 * N) return;
    int k = idx / N, n = idx % N;
    float w = W[idx];
    __nv_bfloat16 h = __float2bfloat16(w);
    __nv_bfloat16 l = __float2bfloat16(w - __bfloat162float(h));
    int c = k >> 6, kk = k & 63, t = n >> 7, nn = n & 127;
    int block = c * (N >> 7) + t;
    unsigned off = SWZ((unsigned)(nn * 128 + kk * 2));
    Hi[block * 8192 + (off >> 1)] = __bfloat16_as_ushort(h);
    Lo[block * 8192 + (off >> 1)] = __bfloat16_as_ushort(l);
}

// ---------------- mma.sync GEMM: C[M x N] = A[M x 256] * W + bias -----------
// CTA: 128m x 128n, 8 warps (warp 32m x 64n), bf16x3 split precision.
// smem (196608 B): A double-buffered [buf][hi/lo] 4x16KB at 0; B all 4 chunks
// [c][hi/lo] 8x16KB at 65536. SW128 swizzle throughout; B arrives pre-swizzled
// via cp.async from the prep images.
__global__ __launch_bounds__(256, 1)
void tc_gemm(const float* __restrict__ A,
             const unsigned short* __restrict__ Whi,
             const unsigned short* __restrict__ Wlo,
             const float* __restrict__ bias, float* __restrict__ C,
             int N)
{
    extern __shared__ __align__(1024) char smem[];
    const int tid  = threadIdx.x;
    const int wid  = tid >> 5, lane = tid & 31;
    const int g    = lane >> 2, t = lane & 3;
    const int quad = lane >> 3, r8 = lane & 7;
    const int warp_m = wid & 3, warp_n = wid >> 2;
    const int m0 = blockIdx.y * 128, n0 = blockIdx.x * 128;
    const int NTI = N >> 7;
    const uint32_t sbase = smem_u32(smem);

    // ---- B: stream all 4 chunks via cp.async (one commit group per chunk) ----
#pragma unroll
    for (int c = 0; c < 4; c++) {
        const char* srcH = (const char*)(Whi + (size_t)(c * NTI + blockIdx.x) * 8192);
        const char* srcL = (const char*)(Wlo + (size_t)(c * NTI + blockIdx.x) * 8192);
        const uint32_t dH = sbase + 65536 + c * 32768;
        const uint32_t dL = dH + 16384;
#pragma unroll
        for (int j = 0; j < 4; j++) {
            const int o = (tid + j * 256) * 16;
            cp16(dH + o, srcH + o);
            cp16(dL + o, srcL + o);
        }
        cp_commit();
    }

    // A global-load mapping: thread handles 8 float4 per chunk
    const int a_r  = tid >> 4;              // rows a_r, then +16 each step? no: idx pattern
    // idx = tid + i*256 -> r = idx>>4 = a_r + i*16, c4 = (tid&15)*4
    const int a_c4 = (tid & 15) * 4;

    float4 av[8];
#define LOAD_A(cc)                                                              \
    {                                                                           \
        _Pragma("unroll")                                                       \
        for (int i = 0; i < 8; i++) {                                           \
            int r = a_r + i * 16;                                               \
            av[i] = *(const float4*)(A + (size_t)(m0 + r) * 256 + (cc) * 64 + a_c4); \
        }                                                                       \
    }
#define STORE_A(buf)                                                            \
    {                                                                           \
        char* bh = smem + (buf) * 32768;                                        \
        char* bl = bh + 16384;                                                  \
        _Pragma("unroll")                                                       \
        for (int i = 0; i < 8; i++) {                                           \
            int r = a_r + i * 16;                                               \
            uint32_t h0, l0, h1, l1;                                            \
            cvt2(av[i].x, av[i].y, h0, l0);                                     \
            cvt2(av[i].z, av[i].w, h1, l1);                                     \
            unsigned off = SWZ((unsigned)(r * 128 + a_c4 * 2));                 \
            *(uint2*)(bh + off) = make_uint2(h0, h1);                           \
            *(uint2*)(bl + off) = make_uint2(l0, l1);                           \
        }                                                                       \
    }

    float acc[2][8][4];
#pragma unroll
    for (int i = 0; i < 2; i++)
#pragma unroll
        for (int j = 0; j < 8; j++)
#pragma unroll
            for (int r = 0; r < 4; r++) acc[i][j][r] = 0.f;

    LOAD_A(0);
    STORE_A(0);
    cp_wait(3);                 // B chunk 0 resident
    __syncthreads();

    for (int c = 0; c < 4; c++) {
        if (c < 3) LOAD_A(c + 1);

        // ---- compute chunk c ----
        const uint32_t saH = sbase + (c & 1) * 32768;
        const uint32_t saL = saH + 16384;
        const uint32_t sbH = sbase + 65536 + c * 32768;
        const uint32_t sbL = sbH + 16384;
#pragma unroll
        for (int kq = 0; kq < 4; kq++) {
            uint32_t ah[2][4], al[2][4];
#pragma unroll
            for (int mt = 0; mt < 2; mt++) {
                const int row = warp_m * 32 + mt * 16 + (quad & 1) * 8 + r8;
                const unsigned off = SWZ((unsigned)(row * 128 + kq * 32 + (quad >> 1) * 16));
                ldsm4(ah[mt], saH + off);
                ldsm4(al[mt], saL + off);
            }
#pragma unroll
            for (int nt2 = 0; nt2 < 4; nt2++) {
                const int brow = warp_n * 64 + nt2 * 16 + (quad >> 1) * 8 + r8;
                const unsigned boff = SWZ((unsigned)(brow * 128 + kq * 32 + (quad & 1) * 16));
                uint32_t bh[4], bl[4];
                ldsm4(bh, sbH + boff);
                ldsm4(bl, sbL + boff);
#pragma unroll
                for (int half = 0; half < 2; half++) {
#pragma unroll
                    for (int mt = 0; mt < 2; mt++) {
                        float* a4 = acc[mt][nt2 * 2 + half];
                        mma_bf16(a4, ah[mt], bh + half * 2);
                        mma_bf16(a4, ah[mt], bl + half * 2);
                        mma_bf16(a4, al[mt], bh + half * 2);
                    }
                }
            }
        }

        if (c < 3) {
            STORE_A((c + 1) & 1);
            cp_wait(2 - c);     // B chunk c+1 resident
        }
        __syncthreads();
    }

    // ---- epilogue ----
#pragma unroll
    for (int mt = 0; mt < 2; mt++) {
#pragma unroll
        for (int nt = 0; nt < 8; nt++) {
            const int row = m0 + warp_m * 32 + mt * 16 + g;
            const int col = n0 + warp_n * 64 + nt * 8 + 2 * t;
            float2 bi = *(const float2*)&bias[col];
            float2 r0 = make_float2(acc[mt][nt][0] + bi.x, acc[mt][nt][1] + bi.y);
            float2 r1 = make_float2(acc[mt][nt][2] + bi.x, acc[mt][nt][3] + bi.y);
            *(float2*)&C[(size_t)row * N + col]       = r0;
            *(float2*)&C[(size_t)(row + 8) * N + col] = r1;
        }
    }
}

// ---------------- fused softmax + bilinear multi-scale sampling ------------
__global__ __launch_bounds__(256, 8)
void msda_sample(const float* __restrict__ refer_bbox)
{
    __shared__ int   s_idx[128][4];
    __shared__ float s_w[128][4];

    const int bq  = blockIdx.x;
    const int b   = bq >> 11;
    const int tid = threadIdx.x;

    if (tid < 128) {
        const int h   = tid >> 4;
        const int sub = tid & 15;
        const int lvl = sub >> 2;
        const int p   = sub & 3;

        float logit = g_attn[(size_t)bq * 128 + h * 16 + sub];
        float mx = logit;
#pragma unroll
        for (int o = 8; o >= 1; o >>= 1)
            mx = fmaxf(mx, __shfl_xor_sync(0xffffffffu, mx, o));
        float e = expf(logit - mx);
        float sm = e;
#pragma unroll
        for (int o = 8; o >= 1; o >>= 1)
            sm += __shfl_xor_sync(0xffffffffu, sm, o);
        const float aw = e / sm;

        const int Hh = c_H[lvl], Ww = c_W[lvl], st = c_start[lvl];
        const float rx = refer_bbox[(size_t)bq * 8 + lvl * 2 + 0];
        const float ry = refer_bbox[(size_t)bq * 8 + lvl * 2 + 1];
        const float ox = g_off[(size_t)bq * DMODEL + h * 32 + lvl * 8 + p * 2 + 0];
        const float oy = g_off[(size_t)bq * DMODEL + h * 32 + lvl * 8 + p * 2 + 1];

        const float x = (rx + ox / (float)Ww) * (float)Ww - 0.5f;
        const float y = (ry + oy / (float)Hh) * (float)Hh - 0.5f;
        const float x0f = floorf(x), y0f = floorf(y);
        const float fx = x - x0f, fy = y - y0f;
        const int x0 = (int)x0f, y0 = (int)y0f;
        const int x1 = x0 + 1,   y1 = y0 + 1;

        const bool vx0 = (x0 >= 0) & (x0 < Ww);
        const bool vx1 = (x1 >= 0) & (x1 < Ww);
        const bool vy0 = (y0 >= 0) & (y0 < Hh);
        const bool vy1 = (y1 >= 0) & (y1 < Hh);

        float w00 = (1.f - fx) * (1.f - fy); if (!(vx0 && vy0)) w00 = 0.f;
        float w10 = fx         * (1.f - fy); if (!(vx1 && vy0)) w10 = 0.f;
        float w01 = (1.f - fx) * fy;         if (!(vx0 && vy1)) w01 = 0.f;
        float w11 = fx         * fy;         if (!(vx1 && vy1)) w11 = 0.f;

        const int cx0 = min(max(x0, 0), Ww - 1);
        const int cx1 = min(max(x1, 0), Ww - 1);
        const int cy0 = min(max(y0, 0), Hh - 1);
        const int cy1 = min(max(y1, 0), Hh - 1);

        const int base = (b * LVTOT + st) * DMODEL + h * 32;
        s_idx[tid][0] = base + (cy0 * Ww + cx0) * DMODEL;
        s_idx[tid][1] = base + (cy0 * Ww + cx1) * DMODEL;
        s_idx[tid][2] = base + (cy1 * Ww + cx0) * DMODEL;
        s_idx[tid][3] = base + (cy1 * Ww + cx1) * DMODEL;
        s_w[tid][0] = w00 * aw;
        s_w[tid][1] = w10 * aw;
        s_w[tid][2] = w01 * aw;
        s_w[tid][3] = w11 * aw;
    }
    __syncthreads();

    const int h = tid >> 5, lane = tid & 31;
    float acc = 0.f;
#pragma unroll
    for (int j = 0; j < 16; j++) {
        const int4   id = *(const int4*)  s_idx[h * 16 + j];
        const float4 w  = *(const float4*)s_w  [h * 16 + j];
        acc = fmaf(w.x, g_v[id.x + lane], acc);
        acc = fmaf(w.y, g_v[id.y + lane], acc);
        acc = fmaf(w.z, g_v[id.z + lane], acc);
        acc = fmaf(w.w, g_v[id.w + lane], acc);
    }
    g_acc[(size_t)bq * DMODEL + h * 32 + lane] = acc;
}

// ---------------- launch -----------------------------------------------
extern "C" void kernel_launch(void* const* d_in, const int* in_sizes, int n_in,
                              void* d_out, int out_size)
{
    const float* query   = (const float*)d_in[0];
    const float* rbbox   = (const float*)d_in[1];
    const float* value   = (const float*)d_in[2];
    const float* W_value = (const float*)d_in[4];
    const float* b_value = (const float*)d_in[5];
    const float* W_off   = (const float*)d_in[6];
    const float* b_off   = (const float*)d_in[7];
    const float* W_attn  = (const float*)d_in[8];
    const float* b_attn  = (const float*)d_in[9];
    const float* W_out   = (const float*)d_in[10];
    const float* b_out   = (const float*)d_in[11];
    float* out = (float*)d_out;

    float *pv, *poff, *pattn, *pacc;
    cudaGetSymbolAddress((void**)&pv,    g_v);
    cudaGetSymbolAddress((void**)&poff,  g_off);
    cudaGetSymbolAddress((void**)&pattn, g_attn);
    cudaGetSymbolAddress((void**)&pacc,  g_acc);

    unsigned short *wvh, *wvl, *woh, *wol, *wah, *wal, *wuh, *wul;
    cudaGetSymbolAddress((void**)&wvh, g_Wv_hi); cudaGetSymbolAddress((void**)&wvl, g_Wv_lo);
    cudaGetSymbolAddress((void**)&woh, g_Wo_hi); cudaGetSymbolAddress((void**)&wol, g_Wo_lo);
    cudaGetSymbolAddress((void**)&wah, g_Wa_hi); cudaGetSymbolAddress((void**)&wal, g_Wa_lo);
    cudaGetSymbolAddress((void**)&wuh, g_Wu_hi); cudaGetSymbolAddress((void**)&wul, g_Wu_lo);

    static bool attr_done = false;
    if (!attr_done) {
        cudaFuncSetAttribute(tc_gemm, cudaFuncAttributeMaxDynamicSharedMemorySize, 196608);
        attr_done = true;
    }
    const int SMEM = 196608;

    const int Mv = BS * LVTOT;   // 174080
    const int Mq = BS * QLEN;    // 16384

    // 0) weight prep (split + swizzle)
    prep_w<<<256, 256>>>(W_value, 256, wvh, wvl);
    prep_w<<<256, 256>>>(W_off,   256, woh, wol);
    prep_w<<<128, 256>>>(W_attn,  128, wah, wal);
    prep_w<<<256, 256>>>(W_out,   256, wuh, wul);

    // 1) value projection
    tc_gemm<<<dim3(2, Mv / 128), 256, SMEM>>>(value, wvh, wvl, b_value, pv, 256);
    // 2) sampling offsets
    tc_gemm<<<dim3(2, Mq / 128), 256, SMEM>>>(query, woh, wol, b_off, poff, 256);
    // 3) attention logits
    tc_gemm<<<dim3(1, Mq / 128), 256, SMEM>>>(query, wah, wal, b_attn, pattn, 128);
    // 4) softmax + sampling
    msda_sample<<<BS * QLEN, 256>>>(rbbox);
    // 5) output projection
    tc_gemm<<<dim3(2, Mq / 128), 256, SMEM>>>(pacc, wuh, wul, b_out, out, 256);
}

// round 9
// speedup vs baseline: 2.8315x; 1.1132x over previous
#include <cuda_runtime.h>
#include <cuda_bf16.h>
#include <cstdint>
#include <stdint.h>
#include <math.h>

// ---------------- problem constants ----------------------------------------
#define BS     8
#define QLEN   2048
#define NLVL   4
#define DMODEL 256
#define LVTOT  21760    // 128^2+64^2+32^2+16^2

__device__ __constant__ int c_H[NLVL]     = {128, 64, 32, 16};
__device__ __constant__ int c_W[NLVL]     = {128, 64, 32, 16};
__device__ __constant__ int c_start[NLVL] = {0, 16384, 20480, 21504};

// ---------------- scratch (device globals) ----------------------------------
__device__ float g_v      [(size_t)BS * LVTOT * DMODEL];
__device__ float g_offattn[(size_t)BS * QLEN * 384];    // [q][0:256)=off, [256:384)=attn
__device__ float g_acc    [(size_t)BS * QLEN * DMODEL];
__device__ float g_bias_oa[384];

// pre-split, pre-swizzled weight images: [chunk(4)][ntile(N/128)][8192 bf16]
__device__ unsigned short g_Wv_hi[65536], g_Wv_lo[65536];   // N=256
__device__ unsigned short g_Woa_hi[98304], g_Woa_lo[98304]; // N=384 (off|attn)
__device__ unsigned short g_Wu_hi[65536], g_Wu_lo[65536];   // N=256

// ---------------- helpers ----------------------------------------------------
#define SWZ(o) ((o) ^ (((o) >> 3) & 0x70))

__device__ __forceinline__ uint32_t smem_u32(const void* p) {
    return (uint32_t)__cvta_generic_to_shared(p);
}

__device__ __forceinline__ void cp16(uint32_t s, const void* g) {
    asm volatile("cp.async.cg.shared.global [%0], [%1], 16;" :: "r"(s), "l"(g) : "memory");
}
__device__ __forceinline__ void cp_commit() {
    asm volatile("cp.async.commit_group;" ::: "memory");
}
__device__ __forceinline__ void cp_wait(int n) {
    if (n == 0) asm volatile("cp.async.wait_group 0;" ::: "memory");
    else        asm volatile("cp.async.wait_group 1;" ::: "memory");
}

__device__ __forceinline__ void ldsm4(uint32_t* r, uint32_t addr) {
    asm volatile("ldmatrix.sync.aligned.m8n8.x4.shared.b16 {%0,%1,%2,%3}, [%4];"
                 : "=r"(r[0]), "=r"(r[1]), "=r"(r[2]), "=r"(r[3]) : "r"(addr));
}

__device__ __forceinline__ void mma_bf16(float* c, const uint32_t* a, const uint32_t* b)
{
    asm volatile(
        "mma.sync.aligned.m16n8k16.row.col.f32.bf16.bf16.f32 "
        "{%0,%1,%2,%3}, {%4,%5,%6,%7}, {%8,%9}, {%0,%1,%2,%3};\n"
        : "+f"(c[0]), "+f"(c[1]), "+f"(c[2]), "+f"(c[3])
        : "r"(a[0]), "r"(a[1]), "r"(a[2]), "r"(a[3]), "r"(b[0]), "r"(b[1]));
}

__device__ __forceinline__ void cvt2(float x, float y, uint32_t& hi, uint32_t& lo)
{
    __nv_bfloat16 hx = __float2bfloat16(x);
    __nv_bfloat16 hy = __float2bfloat16(y);
    __nv_bfloat16 lx = __float2bfloat16(x - __bfloat162float(hx));
    __nv_bfloat16 ly = __float2bfloat16(y - __bfloat162float(hy));
    hi = (uint32_t)__bfloat16_as_ushort(hx) | ((uint32_t)__bfloat16_as_ushort(hy) << 16);
    lo = (uint32_t)__bfloat16_as_ushort(lx) | ((uint32_t)__bfloat16_as_ushort(ly) << 16);
}

// write one weight element into the split/swizzled tile image
__device__ __forceinline__ void wimg(float w, int k, int n, int N,
                                     unsigned short* __restrict__ Hi,
                                     unsigned short* __restrict__ Lo)
{
    __nv_bfloat16 h = __float2bfloat16(w);
    __nv_bfloat16 l = __float2bfloat16(w - __bfloat162float(h));
    int c = k >> 6, kk = k & 63, tt = n >> 7, nn = n & 127;
    int block = c * (N >> 7) + tt;
    unsigned off = SWZ((unsigned)(nn * 128 + kk * 2));
    Hi[block * 8192 + (off >> 1)] = __bfloat16_as_ushort(h);
    Lo[block * 8192 + (off >> 1)] = __bfloat16_as_ushort(l);
}

// ---------------- single prep kernel: all weights + combined bias -----------
__global__ void prep_all(const float* __restrict__ Wv,
                         const float* __restrict__ Woff,
                         const float* __restrict__ Wattn,
                         const float* __restrict__ Wu,
                         const float* __restrict__ boff,
                         const float* __restrict__ battn)
{
    int e = blockIdx.x * 256 + threadIdx.x;
    if (e < 384) g_bias_oa[e] = (e < 256) ? boff[e] : battn[e - 256];

    if (e < 65536) {                       // W_value: 256x256
        int k = e >> 8, n = e & 255;
        wimg(Wv[e], k, n, 256, g_Wv_hi, g_Wv_lo);
    } else if (e < 65536 + 98304) {        // W_off|W_attn fused: 256x384
        int i = e - 65536;
        int k = i / 384, n = i % 384;
        float w = (n < 256) ? Woff[k * 256 + n] : Wattn[k * 128 + (n - 256)];
        wimg(w, k, n, 384, g_Woa_hi, g_Woa_lo);
    } else if (e < 65536 + 98304 + 65536) { // W_out: 256x256
        int i = e - 65536 - 98304;
        int k = i >> 8, n = i & 255;
        wimg(Wu[i], k, n, 256, g_Wu_hi, g_Wu_lo);
    }
}

// ---------------- mma.sync GEMM: C[M x N] = A[M x 256] * W + bias -----------
// CTA: 128m x 128n, 8 warps (warp 32m x 64n), bf16x3 split precision.
// smem 96KB: A single buffer (hi 16K @0, lo 16K @16384); B 2-deep stream,
// buf b @ 32768+b*32768 (hi 16K, lo 16K). 2 CTAs/SM.
__global__ __launch_bounds__(256, 2)
void tc_gemm(const float* __restrict__ A,
             const unsigned short* __restrict__ Whi,
             const unsigned short* __restrict__ Wlo,
             const float* __restrict__ bias, float* __restrict__ C,
             int N)
{
    extern __shared__ __align__(1024) char smem[];
    const int tid  = threadIdx.x;
    const int wid  = tid >> 5, lane = tid & 31;
    const int g    = lane >> 2, t = lane & 3;
    const int quad = lane >> 3, r8 = lane & 7;
    const int warp_m = wid & 3, warp_n = wid >> 2;
    const int m0 = blockIdx.y * 128, n0 = blockIdx.x * 128;
    const int NTI = N >> 7;
    const uint32_t sbase = smem_u32(smem);

    // ---- B chunk issue (into buf c&1) ----
#define ISSUE_B(cc)                                                             \
    {                                                                           \
        const char* srcH = (const char*)(Whi + (size_t)((cc) * NTI + blockIdx.x) * 8192); \
        const char* srcL = (const char*)(Wlo + (size_t)((cc) * NTI + blockIdx.x) * 8192); \
        const uint32_t dH = sbase + 32768 + ((cc) & 1) * 32768;                 \
        const uint32_t dL = dH + 16384;                                         \
        _Pragma("unroll")                                                       \
        for (int j = 0; j < 4; j++) {                                           \
            const int o = (tid + j * 256) * 16;                                 \
            cp16(dH + o, srcH + o);                                             \
            cp16(dL + o, srcL + o);                                             \
        }                                                                       \
        cp_commit();                                                            \
    }

    const int a_r  = tid >> 4;
    const int a_c4 = (tid & 15) * 4;

    float4 av[8];
#define LOAD_A(cc)                                                              \
    {                                                                           \
        _Pragma("unroll")                                                       \
        for (int i = 0; i < 8; i++) {                                           \
            int r = a_r + i * 16;                                               \
            av[i] = *(const float4*)(A + (size_t)(m0 + r) * 256 + (cc) * 64 + a_c4); \
        }                                                                       \
    }
#define STORE_A()                                                               \
    {                                                                           \
        char* bh = smem;                                                        \
        char* bl = smem + 16384;                                                \
        _Pragma("unroll")                                                       \
        for (int i = 0; i < 8; i++) {                                           \
            int r = a_r + i * 16;                                               \
            uint32_t h0, l0, h1, l1;                                            \
            cvt2(av[i].x, av[i].y, h0, l0);                                     \
            cvt2(av[i].z, av[i].w, h1, l1);                                     \
            unsigned off = SWZ((unsigned)(r * 128 + a_c4 * 2));                 \
            *(uint2*)(bh + off) = make_uint2(h0, h1);                           \
            *(uint2*)(bl + off) = make_uint2(l0, l1);                           \
        }                                                                       \
    }

    float acc[2][8][4];
#pragma unroll
    for (int i = 0; i < 2; i++)
#pragma unroll
        for (int j = 0; j < 8; j++)
#pragma unroll
            for (int r = 0; r < 4; r++) acc[i][j][r] = 0.f;

    // ---- prologue: B0,B1 in flight; A chunk 0 staged ----
    ISSUE_B(0);
    ISSUE_B(1);
    LOAD_A(0);
    STORE_A();
    cp_wait(1);                 // B0 resident (pending <= B1)
    __syncthreads();

    for (int c = 0; c < 4; c++) {
        if (c < 3) LOAD_A(c + 1);   // LDG in flight during compute

        // ---- compute chunk c ----
        const uint32_t saH = sbase;
        const uint32_t saL = sbase + 16384;
        const uint32_t sbH = sbase + 32768 + (c & 1) * 32768;
        const uint32_t sbL = sbH + 16384;
#pragma unroll
        for (int kq = 0; kq < 4; kq++) {
            uint32_t ah[2][4], al[2][4];
#pragma unroll
            for (int mt = 0; mt < 2; mt++) {
                const int row = warp_m * 32 + mt * 16 + (quad & 1) * 8 + r8;
                const unsigned off = SWZ((unsigned)(row * 128 + kq * 32 + (quad >> 1) * 16));
                ldsm4(ah[mt], saH + off);
                ldsm4(al[mt], saL + off);
            }
#pragma unroll
            for (int nt2 = 0; nt2 < 4; nt2++) {
                const int brow = warp_n * 64 + nt2 * 16 + (quad >> 1) * 8 + r8;
                const unsigned boff = SWZ((unsigned)(brow * 128 + kq * 32 + (quad & 1) * 16));
                uint32_t bh[4], bl[4];
                ldsm4(bh, sbH + boff);
                ldsm4(bl, sbL + boff);
#pragma unroll
                for (int half = 0; half < 2; half++) {
#pragma unroll
                    for (int mt = 0; mt < 2; mt++) {
                        float* a4 = acc[mt][nt2 * 2 + half];
                        mma_bf16(a4, ah[mt], bh + half * 2);
                        mma_bf16(a4, ah[mt], bl + half * 2);
                        mma_bf16(a4, al[mt], bh + half * 2);
                    }
                }
            }
        }
        __syncthreads();        // done reading A buf + B buf c&1

        if (c < 3) {
            STORE_A();                       // refill A buffer
            if (c + 2 < 4) ISSUE_B(c + 2);   // reuse B buf c&1
            cp_wait((c + 2 < 4) ? 1 : 0);    // B(c+1) resident
            __syncthreads();
        }
    }

    // ---- epilogue ----
#pragma unroll
    for (int mt = 0; mt < 2; mt++) {
#pragma unroll
        for (int nt = 0; nt < 8; nt++) {
            const int row = m0 + warp_m * 32 + mt * 16 + g;
            const int col = n0 + warp_n * 64 + nt * 8 + 2 * t;
            float2 bi = *(const float2*)&bias[col];
            float2 r0 = make_float2(acc[mt][nt][0] + bi.x, acc[mt][nt][1] + bi.y);
            float2 r1 = make_float2(acc[mt][nt][2] + bi.x, acc[mt][nt][3] + bi.y);
            *(float2*)&C[(size_t)row * N + col]       = r0;
            *(float2*)&C[(size_t)(row + 8) * N + col] = r1;
        }
    }
}

// ---------------- fused softmax + bilinear multi-scale sampling ------------
// reads off/attn from combined g_offattn (row stride 384)
__global__ __launch_bounds__(256, 8)
void msda_sample(const float* __restrict__ refer_bbox)
{
    __shared__ int   s_idx[128][4];
    __shared__ float s_w[128][4];

    const int bq  = blockIdx.x;
    const int b   = bq >> 11;
    const int tid = threadIdx.x;

    if (tid < 128) {
        const int h   = tid >> 4;
        const int sub = tid & 15;
        const int lvl = sub >> 2;
        const int p   = sub & 3;

        const float* qrow = g_offattn + (size_t)bq * 384;

        float logit = qrow[256 + h * 16 + sub];
        float mx = logit;
#pragma unroll
        for (int o = 8; o >= 1; o >>= 1)
            mx = fmaxf(mx, __shfl_xor_sync(0xffffffffu, mx, o));
        float e = expf(logit - mx);
        float sm = e;
#pragma unroll
        for (int o = 8; o >= 1; o >>= 1)
            sm += __shfl_xor_sync(0xffffffffu, sm, o);
        const float aw = e / sm;

        const int Hh = c_H[lvl], Ww = c_W[lvl], st = c_start[lvl];
        const float rx = refer_bbox[(size_t)bq * 8 + lvl * 2 + 0];
        const float ry = refer_bbox[(size_t)bq * 8 + lvl * 2 + 1];
        const float ox = qrow[h * 32 + lvl * 8 + p * 2 + 0];
        const float oy = qrow[h * 32 + lvl * 8 + p * 2 + 1];

        const float x = (rx + ox / (float)Ww) * (float)Ww - 0.5f;
        const float y = (ry + oy / (float)Hh) * (float)Hh - 0.5f;
        const float x0f = floorf(x), y0f = floorf(y);
        const float fx = x - x0f, fy = y - y0f;
        const int x0 = (int)x0f, y0 = (int)y0f;
        const int x1 = x0 + 1,   y1 = y0 + 1;

        const bool vx0 = (x0 >= 0) & (x0 < Ww);
        const bool vx1 = (x1 >= 0) & (x1 < Ww);
        const bool vy0 = (y0 >= 0) & (y0 < Hh);
        const bool vy1 = (y1 >= 0) & (y1 < Hh);

        float w00 = (1.f - fx) * (1.f - fy); if (!(vx0 && vy0)) w00 = 0.f;
        float w10 = fx         * (1.f - fy); if (!(vx1 && vy0)) w10 = 0.f;
        float w01 = (1.f - fx) * fy;         if (!(vx0 && vy1)) w01 = 0.f;
        float w11 = fx         * fy;         if (!(vx1 && vy1)) w11 = 0.f;

        const int cx0 = min(max(x0, 0), Ww - 1);
        const int cx1 = min(max(x1, 0), Ww - 1);
        const int cy0 = min(max(y0, 0), Hh - 1);
        const int cy1 = min(max(y1, 0), Hh - 1);

        const int base = (b * LVTOT + st) * DMODEL + h * 32;
        s_idx[tid][0] = base + (cy0 * Ww + cx0) * DMODEL;
        s_idx[tid][1] = base + (cy0 * Ww + cx1) * DMODEL;
        s_idx[tid][2] = base + (cy1 * Ww + cx0) * DMODEL;
        s_idx[tid][3] = base + (cy1 * Ww + cx1) * DMODEL;
        s_w[tid][0] = w00 * aw;
        s_w[tid][1] = w10 * aw;
        s_w[tid][2] = w01 * aw;
        s_w[tid][3] = w11 * aw;
    }
    __syncthreads();

    const int h = tid >> 5, lane = tid & 31;
    float acc = 0.f;
#pragma unroll
    for (int j = 0; j < 16; j++) {
        const int4   id = *(const int4*)  s_idx[h * 16 + j];
        const float4 w  = *(const float4*)s_w  [h * 16 + j];
        acc = fmaf(w.x, g_v[id.x + lane], acc);
        acc = fmaf(w.y, g_v[id.y + lane], acc);
        acc = fmaf(w.z, g_v[id.z + lane], acc);
        acc = fmaf(w.w, g_v[id.w + lane], acc);
    }
    g_acc[(size_t)bq * DMODEL + h * 32 + lane] = acc;
}

// ---------------- launch -----------------------------------------------
extern "C" void kernel_launch(void* const* d_in, const int* in_sizes, int n_in,
                              void* d_out, int out_size)
{
    const float* query   = (const float*)d_in[0];
    const float* rbbox   = (const float*)d_in[1];
    const float* value   = (const float*)d_in[2];
    const float* W_value = (const float*)d_in[4];
    const float* b_value = (const float*)d_in[5];
    const float* W_off   = (const float*)d_in[6];
    const float* b_off   = (const float*)d_in[7];
    const float* W_attn  = (const float*)d_in[8];
    const float* b_attn  = (const float*)d_in[9];
    const float* W_out   = (const float*)d_in[10];
    const float* b_out   = (const float*)d_in[11];
    float* out = (float*)d_out;

    float *pv, *poa, *pacc, *pboa;
    cudaGetSymbolAddress((void**)&pv,   g_v);
    cudaGetSymbolAddress((void**)&poa,  g_offattn);
    cudaGetSymbolAddress((void**)&pacc, g_acc);
    cudaGetSymbolAddress((void**)&pboa, g_bias_oa);

    unsigned short *wvh, *wvl, *woah, *woal, *wuh, *wul;
    cudaGetSymbolAddress((void**)&wvh,  g_Wv_hi);  cudaGetSymbolAddress((void**)&wvl,  g_Wv_lo);
    cudaGetSymbolAddress((void**)&woah, g_Woa_hi); cudaGetSymbolAddress((void**)&woal, g_Woa_lo);
    cudaGetSymbolAddress((void**)&wuh,  g_Wu_hi);  cudaGetSymbolAddress((void**)&wul,  g_Wu_lo);

    static bool attr_done = false;
    if (!attr_done) {
        cudaFuncSetAttribute(tc_gemm, cudaFuncAttributeMaxDynamicSharedMemorySize, 98304);
        attr_done = true;
    }
    const int SMEM = 98304;

    const int Mv = BS * LVTOT;   // 174080
    const int Mq = BS * QLEN;    // 16384

    // 0) all weight prep in one launch
    prep_all<<<896, 256>>>(W_value, W_off, W_attn, W_out, b_off, b_attn);

    // 1) value projection
    tc_gemm<<<dim3(2, Mv / 128), 256, SMEM>>>(value, wvh, wvl, b_value, pv, 256);
    // 2+3) fused offsets + attention logits (N=384)
    tc_gemm<<<dim3(3, Mq / 128), 256, SMEM>>>(query, woah, woal, pboa, poa, 384);
    // 4) softmax + sampling
    msda_sample<<<BS * QLEN, 256>>>(rbbox);
    // 5) output projection
    tc_gemm<<<dim3(2, Mq / 128), 256, SMEM>>>(pacc, wuh, wul, b_out, out, 256);
}

// round 11
// speedup vs baseline: 3.9255x; 1.3864x over previous
#include <cuda_runtime.h>
#include <cuda_bf16.h>
#include <cuda_fp16.h>
#include <cstdint>
#include <stdint.h>
#include <math.h>

// ---------------- problem constants ----------------------------------------
#define BS     8
#define QLEN   2048
#define NLVL   4
#define DMODEL 256
#define LVTOT  21760    // 128^2+64^2+32^2+16^2

__device__ __constant__ int c_H[NLVL]     = {128, 64, 32, 16};
__device__ __constant__ int c_W[NLVL]     = {128, 64, 32, 16};
__device__ __constant__ int c_start[NLVL] = {0, 16384, 20480, 21504};

// ---------------- scratch (device globals) ----------------------------------
__device__ __half g_v [(size_t)BS * LVTOT * DMODEL];    // projected values (fp16)
__device__ float g_offattn[(size_t)BS * QLEN * 384];    // [q][0:256)=off, [256:384)=attn
__device__ float g_acc    [(size_t)BS * QLEN * DMODEL];
__device__ float g_bias_oa[384];

// weight images (pre-swizzled): fp16 single for W_value; bf16 hi/lo for others
__device__ __half        g_Wvf  [65536];                 // N=256
__device__ unsigned short g_Woa_hi[98304], g_Woa_lo[98304]; // N=384 (off|attn)
__device__ unsigned short g_Wu_hi[65536], g_Wu_lo[65536];   // N=256

// ---------------- helpers ----------------------------------------------------
#define SWZ(o) ((o) ^ (((o) >> 3) & 0x70))

__device__ __forceinline__ uint32_t smem_u32(const void* p) {
    return (uint32_t)__cvta_generic_to_shared(p);
}

__device__ __forceinline__ void cp16(uint32_t s, const void* g) {
    asm volatile("cp.async.cg.shared.global [%0], [%1], 16;" :: "r"(s), "l"(g) : "memory");
}
__device__ __forceinline__ void cp_commit() {
    asm volatile("cp.async.commit_group;" ::: "memory");
}
__device__ __forceinline__ void cp_wait(int n) {
    if (n == 0) asm volatile("cp.async.wait_group 0;" ::: "memory");
    else        asm volatile("cp.async.wait_group 1;" ::: "memory");
}

__device__ __forceinline__ void ldsm4(uint32_t* r, uint32_t addr) {
    asm volatile("ldmatrix.sync.aligned.m8n8.x4.shared.b16 {%0,%1,%2,%3}, [%4];"
                 : "=r"(r[0]), "=r"(r[1]), "=r"(r[2]), "=r"(r[3]) : "r"(addr));
}

__device__ __forceinline__ void mma_bf16(float* c, const uint32_t* a, const uint32_t* b)
{
    asm volatile(
        "mma.sync.aligned.m16n8k16.row.col.f32.bf16.bf16.f32 "
        "{%0,%1,%2,%3}, {%4,%5,%6,%7}, {%8,%9}, {%0,%1,%2,%3};\n"
        : "+f"(c[0]), "+f"(c[1]), "+f"(c[2]), "+f"(c[3])
        : "r"(a[0]), "r"(a[1]), "r"(a[2]), "r"(a[3]), "r"(b[0]), "r"(b[1]));
}

__device__ __forceinline__ void mma_f16(float* c, const uint32_t* a, const uint32_t* b)
{
    asm volatile(
        "mma.sync.aligned.m16n8k16.row.col.f32.f16.f16.f32 "
        "{%0,%1,%2,%3}, {%4,%5,%6,%7}, {%8,%9}, {%0,%1,%2,%3};\n"
        : "+f"(c[0]), "+f"(c[1]), "+f"(c[2]), "+f"(c[3])
        : "r"(a[0]), "r"(a[1]), "r"(a[2]), "r"(a[3]), "r"(b[0]), "r"(b[1]));
}

__device__ __forceinline__ void cvt2(float x, float y, uint32_t& hi, uint32_t& lo)
{
    __nv_bfloat16 hx = __float2bfloat16(x);
    __nv_bfloat16 hy = __float2bfloat16(y);
    __nv_bfloat16 lx = __float2bfloat16(x - __bfloat162float(hx));
    __nv_bfloat16 ly = __float2bfloat16(y - __bfloat162float(hy));
    hi = (uint32_t)__bfloat16_as_ushort(hx) | ((uint32_t)__bfloat16_as_ushort(hy) << 16);
    lo = (uint32_t)__bfloat16_as_ushort(lx) | ((uint32_t)__bfloat16_as_ushort(ly) << 16);
}

__device__ __forceinline__ uint32_t cvtf16(float x, float y)
{
    __half2 h = __floats2half2_rn(x, y);
    return *(uint32_t*)&h;
}

// bf16 split/swizzled image writer
__device__ __forceinline__ void wimg(float w, int k, int n, int N,
                                     unsigned short* __restrict__ Hi,
                                     unsigned short* __restrict__ Lo)
{
    __nv_bfloat16 h = __float2bfloat16(w);
    __nv_bfloat16 l = __float2bfloat16(w - __bfloat162float(h));
    int c = k >> 6, kk = k & 63, tt = n >> 7, nn = n & 127;
    int block = c * (N >> 7) + tt;
    unsigned off = SWZ((unsigned)(nn * 128 + kk * 2));
    Hi[block * 8192 + (off >> 1)] = __bfloat16_as_ushort(h);
    Lo[block * 8192 + (off >> 1)] = __bfloat16_as_ushort(l);
}

// ---------------- single prep kernel ----------------------------------------
__global__ void prep_all(const float* __restrict__ Wv,
                         const float* __restrict__ Woff,
                         const float* __restrict__ Wattn,
                         const float* __restrict__ Wu,
                         const float* __restrict__ boff,
                         const float* __restrict__ battn)
{
    int e = blockIdx.x * 256 + threadIdx.x;
    if (e < 384) g_bias_oa[e] = (e < 256) ? boff[e] : battn[e - 256];

    if (e < 65536) {                        // W_value -> fp16 image (N=256)
        int k = e >> 8, n = e & 255;
        int c = k >> 6, kk = k & 63, tt = n >> 7, nn = n & 127;
        int block = c * 2 + tt;
        unsigned off = SWZ((unsigned)(nn * 128 + kk * 2));
        g_Wvf[block * 8192 + (off >> 1)] = __float2half_rn(Wv[e]);
    } else if (e < 65536 + 98304) {         // W_off|W_attn fused: 256x384 bf16x2
        int i = e - 65536;
        int k = i / 384, n = i % 384;
        float w = (n < 256) ? Woff[k * 256 + n] : Wattn[k * 128 + (n - 256)];
        wimg(w, k, n, 384, g_Woa_hi, g_Woa_lo);
    } else if (e < 65536 + 98304 + 65536) { // W_out: 256x256 bf16x2
        int i = e - 65536 - 98304;
        int k = i >> 8, n = i & 255;
        wimg(Wu[i], k, n, 256, g_Wu_hi, g_Wu_lo);
    }
}

// ---------------- bf16x3 GEMM (oa + out): C = A*W + bias --------------------
// identical to R9 passing version. smem 96KB, 2 CTAs/SM.
__global__ __launch_bounds__(256, 2)
void tc_gemm(const float* __restrict__ A,
             const unsigned short* __restrict__ Whi,
             const unsigned short* __restrict__ Wlo,
             const float* __restrict__ bias, float* __restrict__ C,
             int N)
{
    extern __shared__ __align__(1024) char smem[];
    const int tid  = threadIdx.x;
    const int wid  = tid >> 5, lane = tid & 31;
    const int g    = lane >> 2, t = lane & 3;
    const int quad = lane >> 3, r8 = lane & 7;
    const int warp_m = wid & 3, warp_n = wid >> 2;
    const int m0 = blockIdx.y * 128, n0 = blockIdx.x * 128;
    const int NTI = N >> 7;
    const uint32_t sbase = smem_u32(smem);

#define ISSUE_B(cc)                                                             \
    {                                                                           \
        const char* srcH = (const char*)(Whi + (size_t)((cc) * NTI + blockIdx.x) * 8192); \
        const char* srcL = (const char*)(Wlo + (size_t)((cc) * NTI + blockIdx.x) * 8192); \
        const uint32_t dH = sbase + 32768 + ((cc) & 1) * 32768;                 \
        const uint32_t dL = dH + 16384;                                         \
        _Pragma("unroll")                                                       \
        for (int j = 0; j < 4; j++) {                                           \
            const int o = (tid + j * 256) * 16;                                 \
            cp16(dH + o, srcH + o);                                             \
            cp16(dL + o, srcL + o);                                             \
        }                                                                       \
        cp_commit();                                                            \
    }

    const int a_r  = tid >> 4;
    const int a_c4 = (tid & 15) * 4;

    float4 av[8];
#define LOAD_A(cc)                                                              \
    {                                                                           \
        _Pragma("unroll")                                                       \
        for (int i = 0; i < 8; i++) {                                           \
            int r = a_r + i * 16;                                               \
            av[i] = *(const float4*)(A + (size_t)(m0 + r) * 256 + (cc) * 64 + a_c4); \
        }                                                                       \
    }
#define STORE_A()                                                               \
    {                                                                           \
        char* bh = smem;                                                        \
        char* bl = smem + 16384;                                                \
        _Pragma("unroll")                                                       \
        for (int i = 0; i < 8; i++) {                                           \
            int r = a_r + i * 16;                                               \
            uint32_t h0, l0, h1, l1;                                            \
            cvt2(av[i].x, av[i].y, h0, l0);                                     \
            cvt2(av[i].z, av[i].w, h1, l1);                                     \
            unsigned off = SWZ((unsigned)(r * 128 + a_c4 * 2));                 \
            *(uint2*)(bh + off) = make_uint2(h0, h1);                           \
            *(uint2*)(bl + off) = make_uint2(l0, l1);                           \
        }                                                                       \
    }

    float acc[2][8][4];
#pragma unroll
    for (int i = 0; i < 2; i++)
#pragma unroll
        for (int j = 0; j < 8; j++)
#pragma unroll
            for (int r = 0; r < 4; r++) acc[i][j][r] = 0.f;

    ISSUE_B(0);
    ISSUE_B(1);
    LOAD_A(0);
    STORE_A();
    cp_wait(1);
    __syncthreads();

    for (int c = 0; c < 4; c++) {
        if (c < 3) LOAD_A(c + 1);

        const uint32_t saH = sbase;
        const uint32_t saL = sbase + 16384;
        const uint32_t sbH = sbase + 32768 + (c & 1) * 32768;
        const uint32_t sbL = sbH + 16384;
#pragma unroll
        for (int kq = 0; kq < 4; kq++) {
            uint32_t ah[2][4], al[2][4];
#pragma unroll
            for (int mt = 0; mt < 2; mt++) {
                const int row = warp_m * 32 + mt * 16 + (quad & 1) * 8 + r8;
                const unsigned off = SWZ((unsigned)(row * 128 + kq * 32 + (quad >> 1) * 16));
                ldsm4(ah[mt], saH + off);
                ldsm4(al[mt], saL + off);
            }
#pragma unroll
            for (int nt2 = 0; nt2 < 4; nt2++) {
                const int brow = warp_n * 64 + nt2 * 16 + (quad >> 1) * 8 + r8;
                const unsigned boff = SWZ((unsigned)(brow * 128 + kq * 32 + (quad & 1) * 16));
                uint32_t bh[4], bl[4];
                ldsm4(bh, sbH + boff);
                ldsm4(bl, sbL + boff);
#pragma unroll
                for (int half = 0; half < 2; half++) {
#pragma unroll
                    for (int mt = 0; mt < 2; mt++) {
                        float* a4 = acc[mt][nt2 * 2 + half];
                        mma_bf16(a4, ah[mt], bh + half * 2);
                        mma_bf16(a4, ah[mt], bl + half * 2);
                        mma_bf16(a4, al[mt], bh + half * 2);
                    }
                }
            }
        }
        __syncthreads();

        if (c < 3) {
            STORE_A();
            if (c + 2 < 4) ISSUE_B(c + 2);
            cp_wait((c + 2 < 4) ? 1 : 0);
            __syncthreads();
        }
    }

#pragma unroll
    for (int mt = 0; mt < 2; mt++) {
#pragma unroll
        for (int nt = 0; nt < 8; nt++) {
            const int row = m0 + warp_m * 32 + mt * 16 + g;
            const int col = n0 + warp_n * 64 + nt * 8 + 2 * t;
            float2 bi = *(const float2*)&bias[col];
            float2 r0 = make_float2(acc[mt][nt][0] + bi.x, acc[mt][nt][1] + bi.y);
            float2 r1 = make_float2(acc[mt][nt][2] + bi.x, acc[mt][nt][3] + bi.y);
            *(float2*)&C[(size_t)row * N + col]       = r0;
            *(float2*)&C[(size_t)(row + 8) * N + col] = r1;
        }
    }
}

// ---------------- fp16 single-term GEMM (value projection) ------------------
// C_half[M x 256] = A[M x 256] * Wf + bias. smem 48KB: A 16K @0;
// B 2-buf 16K @16384+buf*16384. 2 CTAs/SM.
__global__ __launch_bounds__(256, 2)
void tc_gemm_f16(const float* __restrict__ A,
                 const __half* __restrict__ Wf,
                 const float* __restrict__ bias, __half* __restrict__ C)
{
    extern __shared__ __align__(1024) char smem[];
    const int tid  = threadIdx.x;
    const int wid  = tid >> 5, lane = tid & 31;
    const int g    = lane >> 2, t = lane & 3;
    const int quad = lane >> 3, r8 = lane & 7;
    const int warp_m = wid & 3, warp_n = wid >> 2;
    const int m0 = blockIdx.y * 128, n0 = blockIdx.x * 128;
    const uint32_t sbase = smem_u32(smem);

#define ISSUE_BF(cc)                                                            \
    {                                                                           \
        const char* src = (const char*)(Wf + (size_t)((cc) * 2 + blockIdx.x) * 8192); \
        const uint32_t d = sbase + 16384 + ((cc) & 1) * 16384;                  \
        _Pragma("unroll")                                                       \
        for (int j = 0; j < 4; j++) {                                           \
            const int o = (tid + j * 256) * 16;                                 \
            cp16(d + o, src + o);                                               \
        }                                                                       \
        cp_commit();                                                            \
    }

    const int a_r  = tid >> 4;
    const int a_c4 = (tid & 15) * 4;

    float4 av[8];
#define LOAD_AF(cc)                                                             \
    {                                                                           \
        _Pragma("unroll")                                                       \
        for (int i = 0; i < 8; i++) {                                           \
            int r = a_r + i * 16;                                               \
            av[i] = *(const float4*)(A + (size_t)(m0 + r) * 256 + (cc) * 64 + a_c4); \
        }                                                                       \
    }
#define STORE_AF()                                                              \
    {                                                                           \
        _Pragma("unroll")                                                       \
        for (int i = 0; i < 8; i++) {                                           \
            int r = a_r + i * 16;                                               \
            unsigned off = SWZ((unsigned)(r * 128 + a_c4 * 2));                 \
            *(uint2*)(smem + off) = make_uint2(cvtf16(av[i].x, av[i].y),        \
                                               cvtf16(av[i].z, av[i].w));       \
        }                                                                       \
    }

    float acc[2][8][4];
#pragma unroll
    for (int i = 0; i < 2; i++)
#pragma unroll
        for (int j = 0; j < 8; j++)
#pragma unroll
            for (int r = 0; r < 4; r++) acc[i][j][r] = 0.f;

    ISSUE_BF(0);
    ISSUE_BF(1);
    LOAD_AF(0);
    STORE_AF();
    cp_wait(1);
    __syncthreads();

    for (int c = 0; c < 4; c++) {
        if (c < 3) LOAD_AF(c + 1);

        const uint32_t sa = sbase;
        const uint32_t sb = sbase + 16384 + (c & 1) * 16384;
#pragma unroll
        for (int kq = 0; kq < 4; kq++) {
            uint32_t ah[2][4];
#pragma unroll
            for (int mt = 0; mt < 2; mt++) {
                const int row = warp_m * 32 + mt * 16 + (quad & 1) * 8 + r8;
                const unsigned off = SWZ((unsigned)(row * 128 + kq * 32 + (quad >> 1) * 16));
                ldsm4(ah[mt], sa + off);
            }
#pragma unroll
            for (int nt2 = 0; nt2 < 4; nt2++) {
                const int brow = warp_n * 64 + nt2 * 16 + (quad >> 1) * 8 + r8;
                const unsigned boff = SWZ((unsigned)(brow * 128 + kq * 32 + (quad & 1) * 16));
                uint32_t bh[4];
                ldsm4(bh, sb + boff);
#pragma unroll
                for (int half = 0; half < 2; half++) {
#pragma unroll
                    for (int mt = 0; mt < 2; mt++) {
                        mma_f16(acc[mt][nt2 * 2 + half], ah[mt], bh + half * 2);
                    }
                }
            }
        }
        __syncthreads();

        if (c < 3) {
            STORE_AF();
            if (c + 2 < 4) ISSUE_BF(c + 2);
            cp_wait((c + 2 < 4) ? 1 : 0);
            __syncthreads();
        }
    }

    // epilogue: add bias, store fp16
#pragma unroll
    for (int mt = 0; mt < 2; mt++) {
#pragma unroll
        for (int nt = 0; nt < 8; nt++) {
            const int row = m0 + warp_m * 32 + mt * 16 + g;
            const int col = n0 + warp_n * 64 + nt * 8 + 2 * t;
            float2 bi = *(const float2*)&bias[col];
            __half2 h0 = __floats2half2_rn(acc[mt][nt][0] + bi.x, acc[mt][nt][1] + bi.y);
            __half2 h1 = __floats2half2_rn(acc[mt][nt][2] + bi.x, acc[mt][nt][3] + bi.y);
            *(__half2*)&C[(size_t)row * 256 + col]       = h0;
            *(__half2*)&C[(size_t)(row + 8) * 256 + col] = h1;
        }
    }
}

// ---------------- fused softmax + bilinear multi-scale sampling ------------
__global__ __launch_bounds__(256, 8)
void msda_sample(const float* __restrict__ refer_bbox)
{
    __shared__ int   s_idx[128][4];
    __shared__ float s_w[128][4];

    const int bq  = blockIdx.x;
    const int b   = bq >> 11;
    const int tid = threadIdx.x;

    if (tid < 128) {
        const int h   = tid >> 4;
        const int sub = tid & 15;
        const int lvl = sub >> 2;
        const int p   = sub & 3;

        const float* qrow = g_offattn + (size_t)bq * 384;

        float logit = qrow[256 + h * 16 + sub];
        float mx = logit;
#pragma unroll
        for (int o = 8; o >= 1; o >>= 1)
            mx = fmaxf(mx, __shfl_xor_sync(0xffffffffu, mx, o));
        float e = expf(logit - mx);
        float sm = e;
#pragma unroll
        for (int o = 8; o >= 1; o >>= 1)
            sm += __shfl_xor_sync(0xffffffffu, sm, o);
        const float aw = e / sm;

        const int Hh = c_H[lvl], Ww = c_W[lvl], st = c_start[lvl];
        const float rx = refer_bbox[(size_t)bq * 8 + lvl * 2 + 0];
        const float ry = refer_bbox[(size_t)bq * 8 + lvl * 2 + 1];
        const float ox = qrow[h * 32 + lvl * 8 + p * 2 + 0];
        const float oy = qrow[h * 32 + lvl * 8 + p * 2 + 1];

        const float x = (rx + ox / (float)Ww) * (float)Ww - 0.5f;
        const float y = (ry + oy / (float)Hh) * (float)Hh - 0.5f;
        const float x0f = floorf(x), y0f = floorf(y);
        const float fx = x - x0f, fy = y - y0f;
        const int x0 = (int)x0f, y0 = (int)y0f;
        const int x1 = x0 + 1,   y1 = y0 + 1;

        const bool vx0 = (x0 >= 0) & (x0 < Ww);
        const bool vx1 = (x1 >= 0) & (x1 < Ww);
        const bool vy0 = (y0 >= 0) & (y0 < Hh);
        const bool vy1 = (y1 >= 0) & (y1 < Hh);

        float w00 = (1.f - fx) * (1.f - fy); if (!(vx0 && vy0)) w00 = 0.f;
        float w10 = fx         * (1.f - fy); if (!(vx1 && vy0)) w10 = 0.f;
        float w01 = (1.f - fx) * fy;         if (!(vx0 && vy1)) w01 = 0.f;
        float w11 = fx         * fy;         if (!(vx1 && vy1)) w11 = 0.f;

        const int cx0 = min(max(x0, 0), Ww - 1);
        const int cx1 = min(max(x1, 0), Ww - 1);
        const int cy0 = min(max(y0, 0), Hh - 1);
        const int cy1 = min(max(y1, 0), Hh - 1);

        const int base = (b * LVTOT + st) * DMODEL + h * 32;
        s_idx[tid][0] = base + (cy0 * Ww + cx0) * DMODEL;
        s_idx[tid][1] = base + (cy0 * Ww + cx1) * DMODEL;
        s_idx[tid][2] = base + (cy1 * Ww + cx0) * DMODEL;
        s_idx[tid][3] = base + (cy1 * Ww + cx1) * DMODEL;
        s_w[tid][0] = w00 * aw;
        s_w[tid][1] = w10 * aw;
        s_w[tid][2] = w01 * aw;
        s_w[tid][3] = w11 * aw;
    }
    __syncthreads();

    const int h = tid >> 5, lane = tid & 31;
    float acc = 0.f;
#pragma unroll
    for (int j = 0; j < 16; j++) {
        const int4   id = *(const int4*)  s_idx[h * 16 + j];
        const float4 w  = *(const float4*)s_w  [h * 16 + j];
        acc = fmaf(w.x, __half2float(g_v[id.x + lane]), acc);
        acc = fmaf(w.y, __half2float(g_v[id.y + lane]), acc);
        acc = fmaf(w.z, __half2float(g_v[id.z + lane]), acc);
        acc = fmaf(w.w, __half2float(g_v[id.w + lane]), acc);
    }
    g_acc[(size_t)bq * DMODEL + h * 32 + lane] = acc;
}

// ---------------- launch -----------------------------------------------
extern "C" void kernel_launch(void* const* d_in, const int* in_sizes, int n_in,
                              void* d_out, int out_size)
{
    const float* query   = (const float*)d_in[0];
    const float* rbbox   = (const float*)d_in[1];
    const float* value   = (const float*)d_in[2];
    const float* W_value = (const float*)d_in[4];
    const float* b_value = (const float*)d_in[5];
    const float* W_off   = (const float*)d_in[6];
    const float* b_off   = (const float*)d_in[7];
    const float* W_attn  = (const float*)d_in[8];
    const float* b_attn  = (const float*)d_in[9];
    const float* W_out   = (const float*)d_in[10];
    const float* b_out   = (const float*)d_in[11];
    float* out = (float*)d_out;

    __half* pv;
    float *poa, *pacc, *pboa;
    cudaGetSymbolAddress((void**)&pv,   g_v);
    cudaGetSymbolAddress((void**)&poa,  g_offattn);
    cudaGetSymbolAddress((void**)&pacc, g_acc);
    cudaGetSymbolAddress((void**)&pboa, g_bias_oa);

    __half* wvf;
    unsigned short *woah, *woal, *wuh, *wul;
    cudaGetSymbolAddress((void**)&wvf,  g_Wvf);
    cudaGetSymbolAddress((void**)&woah, g_Woa_hi); cudaGetSymbolAddress((void**)&woal, g_Woa_lo);
    cudaGetSymbolAddress((void**)&wuh,  g_Wu_hi);  cudaGetSymbolAddress((void**)&wul,  g_Wu_lo);

    static bool attr_done = false;
    if (!attr_done) {
        cudaFuncSetAttribute(tc_gemm,     cudaFuncAttributeMaxDynamicSharedMemorySize, 98304);
        cudaFuncSetAttribute(tc_gemm_f16, cudaFuncAttributeMaxDynamicSharedMemorySize, 49152);
        attr_done = true;
    }

    const int Mv = BS * LVTOT;   // 174080
    const int Mq = BS * QLEN;    // 16384

    // 0) all weight prep in one launch
    prep_all<<<896, 256>>>(W_value, W_off, W_attn, W_out, b_off, b_attn);

    // 1) value projection (fp16 single-term, fp16 output)
    tc_gemm_f16<<<dim3(2, Mv / 128), 256, 49152>>>(value, wvf, b_value, pv);
    // 2+3) fused offsets + attention logits (N=384, bf16x3)
    tc_gemm<<<dim3(3, Mq / 128), 256, 98304>>>(query, woah, woal, pboa, poa, 384);
    // 4) softmax + sampling
    msda_sample<<<BS * QLEN, 256>>>(rbbox);
    // 5) output projection (bf16x3)
    tc_gemm<<<dim3(2, Mq / 128), 256, 98304>>>(pacc, wuh, wul, b_out, out, 256);
}

// round 12
// speedup vs baseline: 3.9582x; 1.0083x over previous
#include <cuda_runtime.h>
#include <cuda_bf16.h>
#include <cuda_fp16.h>
#include <cstdint>
#include <stdint.h>
#include <math.h>

// ---------------- problem constants ----------------------------------------
#define BS     8
#define QLEN   2048
#define NLVL   4
#define DMODEL 256
#define LVTOT  21760    // 128^2+64^2+32^2+16^2

__device__ __constant__ int c_H[NLVL]     = {128, 64, 32, 16};
__device__ __constant__ int c_W[NLVL]     = {128, 64, 32, 16};
__device__ __constant__ int c_start[NLVL] = {0, 16384, 20480, 21504};

// ---------------- scratch (device globals) ----------------------------------
__device__ __half g_v [(size_t)BS * LVTOT * DMODEL];    // projected values (fp16)
__device__ float g_offattn[(size_t)BS * QLEN * 384];    // [q][0:256)=off, [256:384)=attn
__device__ float g_acc    [(size_t)BS * QLEN * DMODEL];
__device__ float g_bias_oa[384];

// weight images (pre-swizzled): fp16 single for W_value; bf16 hi/lo for others
__device__ __half         g_Wvf  [65536];                   // N=256
__device__ unsigned short g_Woa_hi[98304], g_Woa_lo[98304]; // N=384 (off|attn)
__device__ unsigned short g_Wu_hi[65536], g_Wu_lo[65536];   // N=256

// ---------------- helpers ----------------------------------------------------
#define SWZ(o) ((o) ^ (((o) >> 3) & 0x70))

__device__ __forceinline__ uint32_t smem_u32(const void* p) {
    return (uint32_t)__cvta_generic_to_shared(p);
}

__device__ __forceinline__ void cp16(uint32_t s, const void* g) {
    asm volatile("cp.async.cg.shared.global [%0], [%1], 16;" :: "r"(s), "l"(g) : "memory");
}
__device__ __forceinline__ void cp_commit() {
    asm volatile("cp.async.commit_group;" ::: "memory");
}
__device__ __forceinline__ void cp_wait(int n) {
    if (n == 0) asm volatile("cp.async.wait_group 0;" ::: "memory");
    else        asm volatile("cp.async.wait_group 1;" ::: "memory");
}

__device__ __forceinline__ void ldsm4(uint32_t* r, uint32_t addr) {
    asm volatile("ldmatrix.sync.aligned.m8n8.x4.shared.b16 {%0,%1,%2,%3}, [%4];"
                 : "=r"(r[0]), "=r"(r[1]), "=r"(r[2]), "=r"(r[3]) : "r"(addr));
}

__device__ __forceinline__ void mma_bf16(float* c, const uint32_t* a, const uint32_t* b)
{
    asm volatile(
        "mma.sync.aligned.m16n8k16.row.col.f32.bf16.bf16.f32 "
        "{%0,%1,%2,%3}, {%4,%5,%6,%7}, {%8,%9}, {%0,%1,%2,%3};\n"
        : "+f"(c[0]), "+f"(c[1]), "+f"(c[2]), "+f"(c[3])
        : "r"(a[0]), "r"(a[1]), "r"(a[2]), "r"(a[3]), "r"(b[0]), "r"(b[1]));
}

__device__ __forceinline__ void mma_f16(float* c, const uint32_t* a, const uint32_t* b)
{
    asm volatile(
        "mma.sync.aligned.m16n8k16.row.col.f32.f16.f16.f32 "
        "{%0,%1,%2,%3}, {%4,%5,%6,%7}, {%8,%9}, {%0,%1,%2,%3};\n"
        : "+f"(c[0]), "+f"(c[1]), "+f"(c[2]), "+f"(c[3])
        : "r"(a[0]), "r"(a[1]), "r"(a[2]), "r"(a[3]), "r"(b[0]), "r"(b[1]));
}

__device__ __forceinline__ void cvt2(float x, float y, uint32_t& hi, uint32_t& lo)
{
    __nv_bfloat16 hx = __float2bfloat16(x);
    __nv_bfloat16 hy = __float2bfloat16(y);
    __nv_bfloat16 lx = __float2bfloat16(x - __bfloat162float(hx));
    __nv_bfloat16 ly = __float2bfloat16(y - __bfloat162float(hy));
    hi = (uint32_t)__bfloat16_as_ushort(hx) | ((uint32_t)__bfloat16_as_ushort(hy) << 16);
    lo = (uint32_t)__bfloat16_as_ushort(lx) | ((uint32_t)__bfloat16_as_ushort(ly) << 16);
}

__device__ __forceinline__ uint32_t cvtf16(float x, float y)
{
    __half2 h = __floats2half2_rn(x, y);
    return *(uint32_t*)&h;
}

// bf16 split/swizzled image writer
__device__ __forceinline__ void wimg(float w, int k, int n, int N,
                                     unsigned short* __restrict__ Hi,
                                     unsigned short* __restrict__ Lo)
{
    __nv_bfloat16 h = __float2bfloat16(w);
    __nv_bfloat16 l = __float2bfloat16(w - __bfloat162float(h));
    int c = k >> 6, kk = k & 63, tt = n >> 7, nn = n & 127;
    int block = c * (N >> 7) + tt;
    unsigned off = SWZ((unsigned)(nn * 128 + kk * 2));
    Hi[block * 8192 + (off >> 1)] = __bfloat16_as_ushort(h);
    Lo[block * 8192 + (off >> 1)] = __bfloat16_as_ushort(l);
}

// ---------------- single prep kernel ----------------------------------------
__global__ void prep_all(const float* __restrict__ Wv,
                         const float* __restrict__ Woff,
                         const float* __restrict__ Wattn,
                         const float* __restrict__ Wu,
                         const float* __restrict__ boff,
                         const float* __restrict__ battn)
{
    int e = blockIdx.x * 256 + threadIdx.x;
    if (e < 384) g_bias_oa[e] = (e < 256) ? boff[e] : battn[e - 256];

    if (e < 65536) {                        // W_value -> fp16 image (N=256)
        int k = e >> 8, n = e & 255;
        int c = k >> 6, kk = k & 63, tt = n >> 7, nn = n & 127;
        int block = c * 2 + tt;
        unsigned off = SWZ((unsigned)(nn * 128 + kk * 2));
        g_Wvf[block * 8192 + (off >> 1)] = __float2half_rn(Wv[e]);
    } else if (e < 65536 + 98304) {         // W_off|W_attn fused: 256x384 bf16x2
        int i = e - 65536;
        int k = i / 384, n = i % 384;
        float w = (n < 256) ? Woff[k * 256 + n] : Wattn[k * 128 + (n - 256)];
        wimg(w, k, n, 384, g_Woa_hi, g_Woa_lo);
    } else if (e < 65536 + 98304 + 65536) { // W_out: 256x256 bf16x2
        int i = e - 65536 - 98304;
        int k = i >> 8, n = i & 255;
        wimg(Wu[i], k, n, 256, g_Wu_hi, g_Wu_lo);
    }
}

// ---------------- bf16x3 GEMM body (oa + out) -------------------------------
// smem 96KB: A hi 16K @0, lo 16K @16384; B 2-deep 32K @32768+buf*32768.
__device__ __forceinline__ void gemm_bf16x3_body(
    char* smem, int bx, int by,
    const float* __restrict__ A,
    const unsigned short* __restrict__ Whi,
    const unsigned short* __restrict__ Wlo,
    const float* __restrict__ bias, float* __restrict__ C, int N)
{
    const int tid  = threadIdx.x;
    const int wid  = tid >> 5, lane = tid & 31;
    const int g    = lane >> 2, t = lane & 3;
    const int quad = lane >> 3, r8 = lane & 7;
    const int warp_m = wid & 3, warp_n = wid >> 2;
    const int m0 = by * 128, n0 = bx * 128;
    const int NTI = N >> 7;
    const uint32_t sbase = smem_u32(smem);

#define ISSUE_B(cc)                                                             \
    {                                                                           \
        const char* srcH = (const char*)(Whi + (size_t)((cc) * NTI + bx) * 8192); \
        const char* srcL = (const char*)(Wlo + (size_t)((cc) * NTI + bx) * 8192); \
        const uint32_t dH = sbase + 32768 + ((cc) & 1) * 32768;                 \
        const uint32_t dL = dH + 16384;                                         \
        _Pragma("unroll")                                                       \
        for (int j = 0; j < 4; j++) {                                           \
            const int o = (tid + j * 256) * 16;                                 \
            cp16(dH + o, srcH + o);                                             \
            cp16(dL + o, srcL + o);                                             \
        }                                                                       \
        cp_commit();                                                            \
    }

    const int a_r  = tid >> 4;
    const int a_c4 = (tid & 15) * 4;

    float4 av[8];
#define LOAD_A(cc)                                                              \
    {                                                                           \
        _Pragma("unroll")                                                       \
        for (int i = 0; i < 8; i++) {                                           \
            int r = a_r + i * 16;                                               \
            av[i] = *(const float4*)(A + (size_t)(m0 + r) * 256 + (cc) * 64 + a_c4); \
        }                                                                       \
    }
#define STORE_A()                                                               \
    {                                                                           \
        char* bh = smem;                                                        \
        char* bl = smem + 16384;                                                \
        _Pragma("unroll")                                                       \
        for (int i = 0; i < 8; i++) {                                           \
            int r = a_r + i * 16;                                               \
            uint32_t h0, l0, h1, l1;                                            \
            cvt2(av[i].x, av[i].y, h0, l0);                                     \
            cvt2(av[i].z, av[i].w, h1, l1);                                     \
            unsigned off = SWZ((unsigned)(r * 128 + a_c4 * 2));                 \
            *(uint2*)(bh + off) = make_uint2(h0, h1);                           \
            *(uint2*)(bl + off) = make_uint2(l0, l1);                           \
        }                                                                       \
    }

    float acc[2][8][4];
#pragma unroll
    for (int i = 0; i < 2; i++)
#pragma unroll
        for (int j = 0; j < 8; j++)
#pragma unroll
            for (int r = 0; r < 4; r++) acc[i][j][r] = 0.f;

    ISSUE_B(0);
    ISSUE_B(1);
    LOAD_A(0);
    STORE_A();
    cp_wait(1);
    __syncthreads();

    for (int c = 0; c < 4; c++) {
        if (c < 3) LOAD_A(c + 1);

        const uint32_t saH = sbase;
        const uint32_t saL = sbase + 16384;
        const uint32_t sbH = sbase + 32768 + (c & 1) * 32768;
        const uint32_t sbL = sbH + 16384;
#pragma unroll
        for (int kq = 0; kq < 4; kq++) {
            uint32_t ah[2][4], al[2][4];
#pragma unroll
            for (int mt = 0; mt < 2; mt++) {
                const int row = warp_m * 32 + mt * 16 + (quad & 1) * 8 + r8;
                const unsigned off = SWZ((unsigned)(row * 128 + kq * 32 + (quad >> 1) * 16));
                ldsm4(ah[mt], saH + off);
                ldsm4(al[mt], saL + off);
            }
#pragma unroll
            for (int nt2 = 0; nt2 < 4; nt2++) {
                const int brow = warp_n * 64 + nt2 * 16 + (quad >> 1) * 8 + r8;
                const unsigned boff = SWZ((unsigned)(brow * 128 + kq * 32 + (quad & 1) * 16));
                uint32_t bh[4], bl[4];
                ldsm4(bh, sbH + boff);
                ldsm4(bl, sbL + boff);
#pragma unroll
                for (int half = 0; half < 2; half++) {
#pragma unroll
                    for (int mt = 0; mt < 2; mt++) {
                        float* a4 = acc[mt][nt2 * 2 + half];
                        mma_bf16(a4, ah[mt], bh + half * 2);
                        mma_bf16(a4, ah[mt], bl + half * 2);
                        mma_bf16(a4, al[mt], bh + half * 2);
                    }
                }
            }
        }
        __syncthreads();

        if (c < 3) {
            STORE_A();
            if (c + 2 < 4) ISSUE_B(c + 2);
            cp_wait((c + 2 < 4) ? 1 : 0);
            __syncthreads();
        }
    }

#pragma unroll
    for (int mt = 0; mt < 2; mt++) {
#pragma unroll
        for (int nt = 0; nt < 8; nt++) {
            const int row = m0 + warp_m * 32 + mt * 16 + g;
            const int col = n0 + warp_n * 64 + nt * 8 + 2 * t;
            float2 bi = *(const float2*)&bias[col];
            float2 r0 = make_float2(acc[mt][nt][0] + bi.x, acc[mt][nt][1] + bi.y);
            float2 r1 = make_float2(acc[mt][nt][2] + bi.x, acc[mt][nt][3] + bi.y);
            *(float2*)&C[(size_t)row * N + col]       = r0;
            *(float2*)&C[(size_t)(row + 8) * N + col] = r1;
        }
    }
#undef ISSUE_B
#undef LOAD_A
#undef STORE_A
}

// ---------------- fp16 single-term GEMM body (value projection) -------------
// smem 48KB: A 16K @0; B 2-buf 16K @16384+buf*16384.
__device__ __forceinline__ void gemm_f16_body(
    char* smem, int bx, int by,
    const float* __restrict__ A, const __half* __restrict__ Wf,
    const float* __restrict__ bias, __half* __restrict__ C)
{
    const int tid  = threadIdx.x;
    const int wid  = tid >> 5, lane = tid & 31;
    const int g    = lane >> 2, t = lane & 3;
    const int quad = lane >> 3, r8 = lane & 7;
    const int warp_m = wid & 3, warp_n = wid >> 2;
    const int m0 = by * 128, n0 = bx * 128;
    const uint32_t sbase = smem_u32(smem);

#define ISSUE_BF(cc)                                                            \
    {                                                                           \
        const char* src = (const char*)(Wf + (size_t)((cc) * 2 + bx) * 8192);   \
        const uint32_t d = sbase + 16384 + ((cc) & 1) * 16384;                  \
        _Pragma("unroll")                                                       \
        for (int j = 0; j < 4; j++) {                                           \
            const int o = (tid + j * 256) * 16;                                 \
            cp16(d + o, src + o);                                               \
        }                                                                       \
        cp_commit();                                                            \
    }

    const int a_r  = tid >> 4;
    const int a_c4 = (tid & 15) * 4;

    float4 av[8];
#define LOAD_AF(cc)                                                             \
    {                                                                           \
        _Pragma("unroll")                                                       \
        for (int i = 0; i < 8; i++) {                                           \
            int r = a_r + i * 16;                                               \
            av[i] = *(const float4*)(A + (size_t)(m0 + r) * 256 + (cc) * 64 + a_c4); \
        }                                                                       \
    }
#define STORE_AF()                                                              \
    {                                                                           \
        _Pragma("unroll")                                                       \
        for (int i = 0; i < 8; i++) {                                           \
            int r = a_r + i * 16;                                               \
            unsigned off = SWZ((unsigned)(r * 128 + a_c4 * 2));                 \
            *(uint2*)(smem + off) = make_uint2(cvtf16(av[i].x, av[i].y),        \
                                               cvtf16(av[i].z, av[i].w));       \
        }                                                                       \
    }

    float acc[2][8][4];
#pragma unroll
    for (int i = 0; i < 2; i++)
#pragma unroll
        for (int j = 0; j < 8; j++)
#pragma unroll
            for (int r = 0; r < 4; r++) acc[i][j][r] = 0.f;

    ISSUE_BF(0);
    ISSUE_BF(1);
    LOAD_AF(0);
    STORE_AF();
    cp_wait(1);
    __syncthreads();

    for (int c = 0; c < 4; c++) {
        if (c < 3) LOAD_AF(c + 1);

        const uint32_t sa = sbase;
        const uint32_t sb = sbase + 16384 + (c & 1) * 16384;
#pragma unroll
        for (int kq = 0; kq < 4; kq++) {
            uint32_t ah[2][4];
#pragma unroll
            for (int mt = 0; mt < 2; mt++) {
                const int row = warp_m * 32 + mt * 16 + (quad & 1) * 8 + r8;
                const unsigned off = SWZ((unsigned)(row * 128 + kq * 32 + (quad >> 1) * 16));
                ldsm4(ah[mt], sa + off);
            }
#pragma unroll
            for (int nt2 = 0; nt2 < 4; nt2++) {
                const int brow = warp_n * 64 + nt2 * 16 + (quad >> 1) * 8 + r8;
                const unsigned boff = SWZ((unsigned)(brow * 128 + kq * 32 + (quad & 1) * 16));
                uint32_t bh[4];
                ldsm4(bh, sb + boff);
#pragma unroll
                for (int half = 0; half < 2; half++) {
#pragma unroll
                    for (int mt = 0; mt < 2; mt++) {
                        mma_f16(acc[mt][nt2 * 2 + half], ah[mt], bh + half * 2);
                    }
                }
            }
        }
        __syncthreads();

        if (c < 3) {
            STORE_AF();
            if (c + 2 < 4) ISSUE_BF(c + 2);
            cp_wait((c + 2 < 4) ? 1 : 0);
            __syncthreads();
        }
    }

#pragma unroll
    for (int mt = 0; mt < 2; mt++) {
#pragma unroll
        for (int nt = 0; nt < 8; nt++) {
            const int row = m0 + warp_m * 32 + mt * 16 + g;
            const int col = n0 + warp_n * 64 + nt * 8 + 2 * t;
            float2 bi = *(const float2*)&bias[col];
            __half2 h0 = __floats2half2_rn(acc[mt][nt][0] + bi.x, acc[mt][nt][1] + bi.y);
            __half2 h1 = __floats2half2_rn(acc[mt][nt][2] + bi.x, acc[mt][nt][3] + bi.y);
            *(__half2*)&C[(size_t)row * 256 + col]       = h0;
            *(__half2*)&C[(size_t)(row + 8) * 256 + col] = h1;
        }
    }
#undef ISSUE_BF
#undef LOAD_AF
#undef STORE_AF
}

// ---------------- merged kernel: value proj (f16) + oa proj (bf16x3) --------
// blocks [0, 2720): value GEMM, bx=bid&1, by=bid>>1
// blocks [2720, 3104): oa GEMM,  bx=(bid-2720)%3, by=(bid-2720)/3
__global__ __launch_bounds__(256, 2)
void mega_gemm(const float* __restrict__ value, const __half* __restrict__ Wvf,
               const float* __restrict__ b_value, __half* __restrict__ Cv,
               const float* __restrict__ query,
               const unsigned short* __restrict__ Woah,
               const unsigned short* __restrict__ Woal,
               const float* __restrict__ bias_oa, float* __restrict__ Coa)
{
    extern __shared__ __align__(1024) char smem[];
    const int bid = blockIdx.x;
    if (bid < 2720) {
        gemm_f16_body(smem, bid & 1, bid >> 1, value, Wvf, b_value, Cv);
    } else {
        const int t2 = bid - 2720;
        gemm_bf16x3_body(smem, t2 % 3, t2 / 3, query, Woah, Woal, bias_oa, Coa, 384);
    }
}

// ---------------- out projection kernel --------------------------------------
__global__ __launch_bounds__(256, 2)
void out_gemm(const float* __restrict__ A,
              const unsigned short* __restrict__ Whi,
              const unsigned short* __restrict__ Wlo,
              const float* __restrict__ bias, float* __restrict__ C)
{
    extern __shared__ __align__(1024) char smem[];
    gemm_bf16x3_body(smem, blockIdx.x, blockIdx.y, A, Whi, Wlo, bias, C, 256);
}

// ---------------- fused softmax + bilinear sampling (2 queries per block) ---
__global__ __launch_bounds__(256, 8)
void msda_sample2(const float* __restrict__ refer_bbox)
{
    __shared__ int   s_idx[256][4];
    __shared__ float s_w[256][4];

    const int bq0 = blockIdx.x * 2;
    const int tid = threadIdx.x;

    // phase A: all 256 threads; task = (q, h), 16 subtasks each
    {
        const int task = tid >> 4;           // 0..15
        const int q    = task >> 3;          // 0..1
        const int h    = task & 7;
        const int sub  = tid & 15;
        const int lvl  = sub >> 2;
        const int p    = sub & 3;
        const int bq   = bq0 + q;
        const int b    = bq >> 11;

        const float* qrow = g_offattn + (size_t)bq * 384;

        float logit = qrow[256 + h * 16 + sub];
        float mx = logit;
#pragma unroll
        for (int o = 8; o >= 1; o >>= 1)
            mx = fmaxf(mx, __shfl_xor_sync(0xffffffffu, mx, o));
        float e = expf(logit - mx);
        float sm = e;
#pragma unroll
        for (int o = 8; o >= 1; o >>= 1)
            sm += __shfl_xor_sync(0xffffffffu, sm, o);
        const float aw = e / sm;

        const int Hh = c_H[lvl], Ww = c_W[lvl], st = c_start[lvl];
        const float rx = refer_bbox[(size_t)bq * 8 + lvl * 2 + 0];
        const float ry = refer_bbox[(size_t)bq * 8 + lvl * 2 + 1];
        const float ox = qrow[h * 32 + lvl * 8 + p * 2 + 0];
        const float oy = qrow[h * 32 + lvl * 8 + p * 2 + 1];

        const float x = (rx + ox / (float)Ww) * (float)Ww - 0.5f;
        const float y = (ry + oy / (float)Hh) * (float)Hh - 0.5f;
        const float x0f = floorf(x), y0f = floorf(y);
        const float fx = x - x0f, fy = y - y0f;
        const int x0 = (int)x0f, y0 = (int)y0f;
        const int x1 = x0 + 1,   y1 = y0 + 1;

        const bool vx0 = (x0 >= 0) & (x0 < Ww);
        const bool vx1 = (x1 >= 0) & (x1 < Ww);
        const bool vy0 = (y0 >= 0) & (y0 < Hh);
        const bool vy1 = (y1 >= 0) & (y1 < Hh);

        float w00 = (1.f - fx) * (1.f - fy); if (!(vx0 && vy0)) w00 = 0.f;
        float w10 = fx         * (1.f - fy); if (!(vx1 && vy0)) w10 = 0.f;
        float w01 = (1.f - fx) * fy;         if (!(vx0 && vy1)) w01 = 0.f;
        float w11 = fx         * fy;         if (!(vx1 && vy1)) w11 = 0.f;

        const int cx0 = min(max(x0, 0), Ww - 1);
        const int cx1 = min(max(x1, 0), Ww - 1);
        const int cy0 = min(max(y0, 0), Hh - 1);
        const int cy1 = min(max(y1, 0), Hh - 1);

        const int base = (b * LVTOT + st) * DMODEL + h * 32;
        s_idx[tid][0] = base + (cy0 * Ww + cx0) * DMODEL;
        s_idx[tid][1] = base + (cy0 * Ww + cx1) * DMODEL;
        s_idx[tid][2] = base + (cy1 * Ww + cx0) * DMODEL;
        s_idx[tid][3] = base + (cy1 * Ww + cx1) * DMODEL;
        s_w[tid][0] = w00 * aw;
        s_w[tid][1] = w10 * aw;
        s_w[tid][2] = w01 * aw;
        s_w[tid][3] = w11 * aw;
    }
    __syncthreads();

    const int h = tid >> 5, lane = tid & 31;
#pragma unroll
    for (int q = 0; q < 2; q++) {
        float acc = 0.f;
#pragma unroll
        for (int j = 0; j < 16; j++) {
            const int4   id = *(const int4*)  s_idx[q * 128 + h * 16 + j];
            const float4 w  = *(const float4*)s_w  [q * 128 + h * 16 + j];
            acc = fmaf(w.x, __half2float(g_v[id.x + lane]), acc);
            acc = fmaf(w.y, __half2float(g_v[id.y + lane]), acc);
            acc = fmaf(w.z, __half2float(g_v[id.z + lane]), acc);
            acc = fmaf(w.w, __half2float(g_v[id.w + lane]), acc);
        }
        g_acc[(size_t)(bq0 + q) * DMODEL + h * 32 + lane] = acc;
    }
}

// ---------------- launch -----------------------------------------------
extern "C" void kernel_launch(void* const* d_in, const int* in_sizes, int n_in,
                              void* d_out, int out_size)
{
    const float* query   = (const float*)d_in[0];
    const float* rbbox   = (const float*)d_in[1];
    const float* value   = (const float*)d_in[2];
    const float* W_value = (const float*)d_in[4];
    const float* b_value = (const float*)d_in[5];
    const float* W_off   = (const float*)d_in[6];
    const float* b_off   = (const float*)d_in[7];
    const float* W_attn  = (const float*)d_in[8];
    const float* b_attn  = (const float*)d_in[9];
    const float* W_out   = (const float*)d_in[10];
    const float* b_out   = (const float*)d_in[11];
    float* out = (float*)d_out;

    __half* pv;
    float *poa, *pacc, *pboa;
    cudaGetSymbolAddress((void**)&pv,   g_v);
    cudaGetSymbolAddress((void**)&poa,  g_offattn);
    cudaGetSymbolAddress((void**)&pacc, g_acc);
    cudaGetSymbolAddress((void**)&pboa, g_bias_oa);

    __half* wvf;
    unsigned short *woah, *woal, *wuh, *wul;
    cudaGetSymbolAddress((void**)&wvf,  g_Wvf);
    cudaGetSymbolAddress((void**)&woah, g_Woa_hi); cudaGetSymbolAddress((void**)&woal, g_Woa_lo);
    cudaGetSymbolAddress((void**)&wuh,  g_Wu_hi);  cudaGetSymbolAddress((void**)&wul,  g_Wu_lo);

    static bool attr_done = false;
    if (!attr_done) {
        cudaFuncSetAttribute(mega_gemm, cudaFuncAttributeMaxDynamicSharedMemorySize, 98304);
        cudaFuncSetAttribute(out_gemm,  cudaFuncAttributeMaxDynamicSharedMemorySize, 98304);
        attr_done = true;
    }

    const int Mq = BS * QLEN;    // 16384

    // 0) all weight prep in one launch
    prep_all<<<896, 256>>>(W_value, W_off, W_attn, W_out, b_off, b_attn);

    // 1) merged: value projection (blocks 0..2719) + off/attn projection (2720..3103)
    mega_gemm<<<3104, 256, 98304>>>(value, wvf, b_value, pv,
                                    query, woah, woal, pboa, poa);
    // 2) softmax + sampling (2 queries per block)
    msda_sample2<<<BS * QLEN / 2, 256>>>(rbbox);
    // 3) output projection (bf16x3)
    out_gemm<<<dim3(2, Mq / 128), 256, 98304>>>(pacc, wuh, wul, b_out, out);
}

// round 14
// speedup vs baseline: 4.5692x; 1.1544x over previous
#include <cuda_runtime.h>
#include <cuda_fp16.h>
#include <cstdint>
#include <stdint.h>
#include <math.h>

// ---------------- problem constants ----------------------------------------
#define BS     8
#define QLEN   2048
#define NLVL   4
#define DMODEL 256
#define LVTOT  21760    // 128^2+64^2+32^2+16^2

__device__ __constant__ int c_H[NLVL]     = {128, 64, 32, 16};
__device__ __constant__ int c_W[NLVL]     = {128, 64, 32, 16};
__device__ __constant__ int c_start[NLVL] = {0, 16384, 20480, 21504};

// ---------------- scratch (device globals) ----------------------------------
__device__ __half g_v  [(size_t)BS * LVTOT * DMODEL];   // projected values (fp16)
__device__ float  g_offattn[(size_t)BS * QLEN * 384];   // [q][0:256)=off, [256:384)=attn
__device__ __half g_acc[(size_t)BS * QLEN * DMODEL];    // sampled accumulators (fp16)
__device__ float  g_bias_oa[384];

// pre-swizzled fp16 weight images: [chunk(4)][ntile(N/128)][8192 halves]
__device__ __half g_Wvf [65536];    // W_value, N=256
__device__ __half g_Woaf[98304];    // W_off|W_attn, N=384
__device__ __half g_Wuf [65536];    // W_out, N=256

// ---------------- helpers ----------------------------------------------------
#define SWZ(o) ((o) ^ (((o) >> 3) & 0x70))

__device__ __forceinline__ uint32_t smem_u32(const void* p) {
    return (uint32_t)__cvta_generic_to_shared(p);
}

__device__ __forceinline__ void cp16(uint32_t s, const void* g) {
    asm volatile("cp.async.cg.shared.global [%0], [%1], 16;" :: "r"(s), "l"(g) : "memory");
}
__device__ __forceinline__ void cp_commit() {
    asm volatile("cp.async.commit_group;" ::: "memory");
}
__device__ __forceinline__ void cp_wait(int n) {
    if (n == 0) asm volatile("cp.async.wait_group 0;" ::: "memory");
    else        asm volatile("cp.async.wait_group 1;" ::: "memory");
}

__device__ __forceinline__ void ldsm4(uint32_t* r, uint32_t addr) {
    asm volatile("ldmatrix.sync.aligned.m8n8.x4.shared.b16 {%0,%1,%2,%3}, [%4];"
                 : "=r"(r[0]), "=r"(r[1]), "=r"(r[2]), "=r"(r[3]) : "r"(addr));
}

__device__ __forceinline__ void mma_f16(float* c, const uint32_t* a, const uint32_t* b)
{
    asm volatile(
        "mma.sync.aligned.m16n8k16.row.col.f32.f16.f16.f32 "
        "{%0,%1,%2,%3}, {%4,%5,%6,%7}, {%8,%9}, {%0,%1,%2,%3};\n"
        : "+f"(c[0]), "+f"(c[1]), "+f"(c[2]), "+f"(c[3])
        : "r"(a[0]), "r"(a[1]), "r"(a[2]), "r"(a[3]), "r"(b[0]), "r"(b[1]));
}

__device__ __forceinline__ uint32_t cvtf16(float x, float y)
{
    __half2 h = __floats2half2_rn(x, y);
    return *(uint32_t*)&h;
}

// swizzled weight-image index: block = (k/64)*(N/128) + n/128
__device__ __forceinline__ int wimg_idx(int k, int n, int N)
{
    int block = (k >> 6) * (N >> 7) + (n >> 7);
    unsigned off = SWZ((unsigned)((n & 127) * 128 + (k & 63) * 2));
    return block * 8192 + (int)(off >> 1);
}

// ---------------- single prep kernel (all weights fp16 + combined bias) -----
__global__ void prep_all(const float* __restrict__ Wv,
                         const float* __restrict__ Woff,
                         const float* __restrict__ Wattn,
                         const float* __restrict__ Wu,
                         const float* __restrict__ boff,
                         const float* __restrict__ battn)
{
    int e = blockIdx.x * 256 + threadIdx.x;
    if (e < 384) g_bias_oa[e] = (e < 256) ? boff[e] : battn[e - 256];

    if (e < 65536) {                        // W_value + W_out (both 256x256)
        int k = e >> 8, n = e & 255;
        int idx = wimg_idx(k, n, 256);
        g_Wvf[idx] = __float2half_rn(Wv[e]);
        g_Wuf[idx] = __float2half_rn(Wu[e]);
    } else if (e < 65536 + 98304) {         // W_off|W_attn fused: 256x384
        int i = e - 65536;
        int k = i / 384, n = i % 384;
        float w = (n < 256) ? Woff[k * 256 + n] : Wattn[k * 128 + (n - 256)];
        g_Woaf[wimg_idx(k, n, 384)] = __float2half_rn(w);
    }
}

// ---------------- unified fp16 GEMM body -------------------------------------
// C[M x N] = A[M x 256] * W + bias.  CTA 128m x 128n, 8 warps (32m x 64n).
// smem 96KB: A 3-buf 16K @ (c%3)*16384; B 3-buf 16K @ 49152+(c%3)*16384.
// ONE __syncthreads per K-chunk; staging targets buffers retired >=1 barrier ago.
// AHALF: A is fp16 row-major (stride 256 halves) -> staged via swizzled cp.async.
// else:  A is fp32 (stride 256 floats) -> LDG + cvt + STS.
template<bool AHALF, bool CHALF>
__device__ __forceinline__ void gemm_uni(char* smem, int bx, int by,
                                         const void* Ap, const __half* __restrict__ Wf,
                                         const float* __restrict__ bias, void* Cp, int N)
{
    const int tid  = threadIdx.x;
    const int wid  = tid >> 5, lane = tid & 31;
    const int g    = lane >> 2, t = lane & 3;
    const int quad = lane >> 3, r8 = lane & 7;
    const int warp_m = wid & 3, warp_n = wid >> 2;
    const int m0 = by * 128, n0 = bx * 128;
    const int NTI = N >> 7;
    const uint32_t sbase = smem_u32(smem);

    // ---- staging helpers ----
    auto issue_a = [&](int cc) {            // AHALF only: swizzled cp.async
        const char* src = (const char*)Ap + (size_t)m0 * 512 + cc * 128;
        const uint32_t d = sbase + (cc % 3) * 16384;
#pragma unroll
        for (int j = 0; j < 4; j++) {
            int idx = tid + j * 256;        // 0..1023 : 128 rows x 8 16B-blocks
            int r = idx >> 3, blk = idx & 7;
            cp16(d + SWZ((unsigned)(r * 128 + blk * 16)),
                 src + (size_t)r * 512 + blk * 16);
        }
    };
    auto issue_b = [&](int cc) {
        const char* src = (const char*)(Wf + (size_t)(cc * NTI + bx) * 8192);
        const uint32_t d = sbase + 49152 + (cc % 3) * 16384;
#pragma unroll
        for (int j = 0; j < 4; j++) {
            const int o = (tid + j * 256) * 16;
            cp16(d + o, src + o);
        }
    };

    const int a_r  = tid >> 4;
    const int a_c4 = (tid & 15) * 4;
    float4 av[8];
    auto load_a = [&](int cc) {             // fp32 path
#pragma unroll
        for (int i = 0; i < 8; i++) {
            int r = a_r + i * 16;
            av[i] = *(const float4*)((const float*)Ap + (size_t)(m0 + r) * 256 + cc * 64 + a_c4);
        }
    };
    auto store_a = [&](int cc) {
        char* bufp = smem + (cc % 3) * 16384;
#pragma unroll
        for (int i = 0; i < 8; i++) {
            int r = a_r + i * 16;
            unsigned off = SWZ((unsigned)(r * 128 + a_c4 * 2));
            *(uint2*)(bufp + off) = make_uint2(cvtf16(av[i].x, av[i].y),
                                               cvtf16(av[i].z, av[i].w));
        }
    };

    float acc[2][8][4];
#pragma unroll
    for (int i = 0; i < 2; i++)
#pragma unroll
        for (int j = 0; j < 8; j++)
#pragma unroll
            for (int r = 0; r < 4; r++) acc[i][j][r] = 0.f;

    // ---- prologue: groups {A0,B0}, {A1,B1} (A in-group only if AHALF) ----
    if (AHALF) {
        issue_a(0); issue_b(0); cp_commit();
        issue_a(1); issue_b(1); cp_commit();
    } else {
        issue_b(0); cp_commit();
        issue_b(1); cp_commit();
        load_a(0); store_a(0);
    }
    cp_wait(1);                 // group 0 resident
    __syncthreads();

    for (int c = 0; c < 4; c++) {
        if (!AHALF && c < 3) load_a(c + 1);     // LDG in flight behind compute

        const uint32_t sa = sbase + (c % 3) * 16384;
        const uint32_t sb = sbase + 49152 + (c % 3) * 16384;
#pragma unroll
        for (int kq = 0; kq < 4; kq++) {
            uint32_t ah[2][4];
#pragma unroll
            for (int mt = 0; mt < 2; mt++) {
                const int row = warp_m * 32 + mt * 16 + (quad & 1) * 8 + r8;
                const unsigned off = SWZ((unsigned)(row * 128 + kq * 32 + (quad >> 1) * 16));
                ldsm4(ah[mt], sa + off);
            }
#pragma unroll
            for (int nt2 = 0; nt2 < 4; nt2++) {
                const int brow = warp_n * 64 + nt2 * 16 + (quad >> 1) * 8 + r8;
                const unsigned boff = SWZ((unsigned)(brow * 128 + kq * 32 + (quad & 1) * 16));
                uint32_t bh[4];
                ldsm4(bh, sb + boff);
#pragma unroll
                for (int half = 0; half < 2; half++) {
#pragma unroll
                    for (int mt = 0; mt < 2; mt++) {
                        mma_f16(acc[mt][nt2 * 2 + half], ah[mt], bh + half * 2);
                    }
                }
            }
        }

        if (c < 3) {
            // stage c+1 A (fp32 path) into buf (c+1)%3 — last read before the
            // previous barrier; issue group c+2 into bufs (c+2)%3 — same.
            if (!AHALF) store_a(c + 1);
            if (c + 2 < 4) {
                if (AHALF) issue_a(c + 2);
                issue_b(c + 2);
                cp_commit();
            }
            cp_wait((c + 2 < 4) ? 1 : 0);       // group c+1 resident
            __syncthreads();
        }
    }

    // ---- epilogue ----
#pragma unroll
    for (int mt = 0; mt < 2; mt++) {
#pragma unroll
        for (int nt = 0; nt < 8; nt++) {
            const int row = m0 + warp_m * 32 + mt * 16 + g;
            const int col = n0 + warp_n * 64 + nt * 8 + 2 * t;
            float2 bi = *(const float2*)&bias[col];
            float o0 = acc[mt][nt][0] + bi.x, o1 = acc[mt][nt][1] + bi.y;
            float o2 = acc[mt][nt][2] + bi.x, o3 = acc[mt][nt][3] + bi.y;
            if (CHALF) {
                __half* C = (__half*)Cp;
                *(__half2*)&C[(size_t)row * N + col]       = __floats2half2_rn(o0, o1);
                *(__half2*)&C[(size_t)(row + 8) * N + col] = __floats2half2_rn(o2, o3);
            } else {
                float* C = (float*)Cp;
                *(float2*)&C[(size_t)row * N + col]       = make_float2(o0, o1);
                *(float2*)&C[(size_t)(row + 8) * N + col] = make_float2(o2, o3);
            }
        }
    }
}

// ---------------- merged kernel: value proj + oa proj ------------------------
// blocks [0, 2720): value (fp32 A -> fp16 C), bx=bid&1, by=bid>>1
// blocks [2720, 3104): off/attn (fp32 A -> fp32 C, N=384)
__global__ __launch_bounds__(256, 2)
void mega_gemm(const float* __restrict__ value, const __half* __restrict__ Wvf,
               const float* __restrict__ b_value, __half* __restrict__ Cv,
               const float* __restrict__ query, const __half* __restrict__ Woaf,
               const float* __restrict__ bias_oa, float* __restrict__ Coa)
{
    extern __shared__ __align__(1024) char smem[];
    const int bid = blockIdx.x;
    if (bid < 2720) {
        gemm_uni<false, true>(smem, bid & 1, bid >> 1, value, Wvf, b_value, Cv, 256);
    } else {
        const int t2 = bid - 2720;
        gemm_uni<false, false>(smem, t2 % 3, t2 / 3, query, Woaf, bias_oa, Coa, 384);
    }
}

// ---------------- out projection: fp16 A (g_acc) via cp.async ---------------
__global__ __launch_bounds__(256, 2)
void out_gemm(const __half* __restrict__ A, const __half* __restrict__ Wuf,
              const float* __restrict__ bias, float* __restrict__ C)
{
    extern __shared__ __align__(1024) char smem[];
    const int bid = blockIdx.x;
    gemm_uni<true, false>(smem, bid & 1, bid >> 1, A, Wuf, bias, C, 256);
}

// ---------------- fused softmax + bilinear sampling (2 queries per block) ---
__global__ __launch_bounds__(256, 8)
void msda_sample2(const float* __restrict__ refer_bbox)
{
    __shared__ int   s_idx[256][4];
    __shared__ float s_w[256][4];

    const int bq0 = blockIdx.x * 2;
    const int tid = threadIdx.x;

    {
        const int task = tid >> 4;           // 0..15 = (q, h)
        const int q    = task >> 3;
        const int h    = task & 7;
        const int sub  = tid & 15;
        const int lvl  = sub >> 2;
        const int p    = sub & 3;
        const int bq   = bq0 + q;
        const int b    = bq >> 11;

        const float* qrow = g_offattn + (size_t)bq * 384;

        float logit = qrow[256 + h * 16 + sub];
        float mx = logit;
#pragma unroll
        for (int o = 8; o >= 1; o >>= 1)
            mx = fmaxf(mx, __shfl_xor_sync(0xffffffffu, mx, o));
        float e = expf(logit - mx);
        float sm = e;
#pragma unroll
        for (int o = 8; o >= 1; o >>= 1)
            sm += __shfl_xor_sync(0xffffffffu, sm, o);
        const float aw = e / sm;

        const int Hh = c_H[lvl], Ww = c_W[lvl], st = c_start[lvl];
        const float rx = refer_bbox[(size_t)bq * 8 + lvl * 2 + 0];
        const float ry = refer_bbox[(size_t)bq * 8 + lvl * 2 + 1];
        const float ox = qrow[h * 32 + lvl * 8 + p * 2 + 0];
        const float oy = qrow[h * 32 + lvl * 8 + p * 2 + 1];

        const float x = (rx + ox / (float)Ww) * (float)Ww - 0.5f;
        const float y = (ry + oy / (float)Hh) * (float)Hh - 0.5f;
        const float x0f = floorf(x), y0f = floorf(y);
        const float fx = x - x0f, fy = y - y0f;
        const int x0 = (int)x0f, y0 = (int)y0f;
        const int x1 = x0 + 1,   y1 = y0 + 1;

        const bool vx0 = (x0 >= 0) & (x0 < Ww);
        const bool vx1 = (x1 >= 0) & (x1 < Ww);
        const bool vy0 = (y0 >= 0) & (y0 < Hh);
        const bool vy1 = (y1 >= 0) & (y1 < Hh);

        float w00 = (1.f - fx) * (1.f - fy); if (!(vx0 && vy0)) w00 = 0.f;
        float w10 = fx         * (1.f - fy); if (!(vx1 && vy0)) w10 = 0.f;
        float w01 = (1.f - fx) * fy;         if (!(vx0 && vy1)) w01 = 0.f;
        float w11 = fx         * fy;         if (!(vx1 && vy1)) w11 = 0.f;

        const int cx0 = min(max(x0, 0), Ww - 1);
        const int cx1 = min(max(x1, 0), Ww - 1);
        const int cy0 = min(max(y0, 0), Hh - 1);
        const int cy1 = min(max(y1, 0), Hh - 1);

        const int base = (b * LVTOT + st) * DMODEL + h * 32;
        s_idx[tid][0] = base + (cy0 * Ww + cx0) * DMODEL;
        s_idx[tid][1] = base + (cy0 * Ww + cx1) * DMODEL;
        s_idx[tid][2] = base + (cy1 * Ww + cx0) * DMODEL;
        s_idx[tid][3] = base + (cy1 * Ww + cx1) * DMODEL;
        s_w[tid][0] = w00 * aw;
        s_w[tid][1] = w10 * aw;
        s_w[tid][2] = w01 * aw;
        s_w[tid][3] = w11 * aw;
    }
    __syncthreads();

    const int h = tid >> 5, lane = tid & 31;
#pragma unroll
    for (int q = 0; q < 2; q++) {
        float acc = 0.f;
#pragma unroll
        for (int j = 0; j < 16; j++) {
            const int4   id = *(const int4*)  s_idx[q * 128 + h * 16 + j];
            const float4 w  = *(const float4*)s_w  [q * 128 + h * 16 + j];
            acc = fmaf(w.x, __half2float(g_v[id.x + lane]), acc);
            acc = fmaf(w.y, __half2float(g_v[id.y + lane]), acc);
            acc = fmaf(w.z, __half2float(g_v[id.z + lane]), acc);
            acc = fmaf(w.w, __half2float(g_v[id.w + lane]), acc);
        }
        g_acc[(size_t)(bq0 + q) * DMODEL + h * 32 + lane] = __float2half_rn(acc);
    }
}

// ---------------- launch -----------------------------------------------
extern "C" void kernel_launch(void* const* d_in, const int* in_sizes, int n_in,
                              void* d_out, int out_size)
{
    const float* query   = (const float*)d_in[0];
    const float* rbbox   = (const float*)d_in[1];
    const float* value   = (const float*)d_in[2];
    const float* W_value = (const float*)d_in[4];
    const float* b_value = (const float*)d_in[5];
    const float* W_off   = (const float*)d_in[6];
    const float* b_off   = (const float*)d_in[7];
    const float* W_attn  = (const float*)d_in[8];
    const float* b_attn  = (const float*)d_in[9];
    const float* W_out   = (const float*)d_in[10];
    const float* b_out   = (const float*)d_in[11];
    float* out = (float*)d_out;

    __half *pv, *pacc;
    float *poa, *pboa;
    cudaGetSymbolAddress((void**)&pv,   g_v);
    cudaGetSymbolAddress((void**)&poa,  g_offattn);
    cudaGetSymbolAddress((void**)&pacc, g_acc);
    cudaGetSymbolAddress((void**)&pboa, g_bias_oa);

    __half *wvf, *woaf, *wuf;
    cudaGetSymbolAddress((void**)&wvf,  g_Wvf);
    cudaGetSymbolAddress((void**)&woaf, g_Woaf);
    cudaGetSymbolAddress((void**)&wuf,  g_Wuf);

    static bool attr_done = false;
    if (!attr_done) {
        cudaFuncSetAttribute(mega_gemm, cudaFuncAttributeMaxDynamicSharedMemorySize, 98304);
        cudaFuncSetAttribute(out_gemm,  cudaFuncAttributeMaxDynamicSharedMemorySize, 98304);
        attr_done = true;
    }
    const int SMEM = 98304;

    // 0) all weight prep in one launch ((65536+98304)/256 = 640 blocks)
    prep_all<<<640, 256>>>(W_value, W_off, W_attn, W_out, b_off, b_attn);

    // 1) merged: value projection (blocks 0..2719) + off/attn (2720..3103)
    mega_gemm<<<3104, 256, SMEM>>>(value, wvf, b_value, pv,
                                   query, woaf, pboa, poa);
    // 2) softmax + sampling (2 queries per block), fp16 acc out
    msda_sample2<<<BS * QLEN / 2, 256>>>(rbbox);
    // 3) output projection (fp16 A via cp.async)
    out_gemm<<<256, 256, SMEM>>>(pacc, wuf, b_out, out);
}

// round 16
// speedup vs baseline: 5.2741x; 1.1543x over previous
#include <cuda_runtime.h>
#include <cuda_fp16.h>
#include <cstdint>
#include <stdint.h>
#include <math.h>

// ---------------- problem constants ----------------------------------------
#define BS     8
#define QLEN   2048
#define NLVL   4
#define DMODEL 256
#define LVTOT  21760    // 128^2+64^2+32^2+16^2

__device__ __constant__ int c_H[NLVL]     = {128, 64, 32, 16};
__device__ __constant__ int c_W[NLVL]     = {128, 64, 32, 16};
__device__ __constant__ int c_start[NLVL] = {0, 16384, 20480, 21504};

// ---------------- scratch (device globals) ----------------------------------
__device__ __half g_v  [(size_t)BS * LVTOT * DMODEL];   // projected values (fp16)
__device__ float  g_offattn[(size_t)BS * QLEN * 384];   // [q][0:256)=off, [256:384)=attn
__device__ __half g_acc[(size_t)BS * QLEN * DMODEL];    // sampled accumulators (fp16)
__device__ float  g_bias_oa[384];

// pre-swizzled fp16 weight images: [chunk(4)][ntile(N/128)][8192 halves]
__device__ __half g_Wvf [65536];    // W_value, N=256
__device__ __half g_Woaf[98304];    // W_off|W_attn, N=384
__device__ __half g_Wuf [65536];    // W_out, N=256

// ---------------- helpers ----------------------------------------------------
#define SWZ(o) ((o) ^ (((o) >> 3) & 0x70))

__device__ __forceinline__ uint32_t smem_u32(const void* p) {
    return (uint32_t)__cvta_generic_to_shared(p);
}

__device__ __forceinline__ void cp16(uint32_t s, const void* g) {
    asm volatile("cp.async.cg.shared.global [%0], [%1], 16;" :: "r"(s), "l"(g) : "memory");
}
__device__ __forceinline__ void cp_commit() {
    asm volatile("cp.async.commit_group;" ::: "memory");
}
__device__ __forceinline__ void cp_wait(int n) {
    if (n == 0) asm volatile("cp.async.wait_group 0;" ::: "memory");
    else        asm volatile("cp.async.wait_group 1;" ::: "memory");
}

__device__ __forceinline__ void ldsm4(uint32_t* r, uint32_t addr) {
    asm volatile("ldmatrix.sync.aligned.m8n8.x4.shared.b16 {%0,%1,%2,%3}, [%4];"
                 : "=r"(r[0]), "=r"(r[1]), "=r"(r[2]), "=r"(r[3]) : "r"(addr));
}

__device__ __forceinline__ void mma_f16(float* c, const uint32_t* a, const uint32_t* b)
{
    asm volatile(
        "mma.sync.aligned.m16n8k16.row.col.f32.f16.f16.f32 "
        "{%0,%1,%2,%3}, {%4,%5,%6,%7}, {%8,%9}, {%0,%1,%2,%3};\n"
        : "+f"(c[0]), "+f"(c[1]), "+f"(c[2]), "+f"(c[3])
        : "r"(a[0]), "r"(a[1]), "r"(a[2]), "r"(a[3]), "r"(b[0]), "r"(b[1]));
}

__device__ __forceinline__ uint32_t cvtf16(float x, float y)
{
    __half2 h = __floats2half2_rn(x, y);
    return *(uint32_t*)&h;
}

// swizzled weight-image index: block = (k/64)*(N/128) + n/128
__device__ __forceinline__ int wimg_idx(int k, int n, int N)
{
    int block = (k >> 6) * (N >> 7) + (n >> 7);
    unsigned off = SWZ((unsigned)((n & 127) * 128 + (k & 63) * 2));
    return block * 8192 + (int)(off >> 1);
}

// ---------------- single prep kernel (all weights fp16 + combined bias) -----
__global__ void prep_all(const float* __restrict__ Wv,
                         const float* __restrict__ Woff,
                         const float* __restrict__ Wattn,
                         const float* __restrict__ Wu,
                         const float* __restrict__ boff,
                         const float* __restrict__ battn)
{
    int e = blockIdx.x * 256 + threadIdx.x;
    if (e < 384) g_bias_oa[e] = (e < 256) ? boff[e] : battn[e - 256];

    if (e < 65536) {                        // W_value + W_out (both 256x256)
        int k = e >> 8, n = e & 255;
        int idx = wimg_idx(k, n, 256);
        g_Wvf[idx] = __float2half_rn(Wv[e]);
        g_Wuf[idx] = __float2half_rn(Wu[e]);
    } else if (e < 65536 + 98304) {         // W_off|W_attn fused: 256x384
        int i = e - 65536;
        int k = i / 384, n = i % 384;
        float w = (n < 256) ? Woff[k * 256 + n] : Wattn[k * 128 + (n - 256)];
        g_Woaf[wimg_idx(k, n, 384)] = __float2half_rn(w);
    }
}

// ---------------- unified fp16 GEMM body -------------------------------------
// C[M x N] = A[M x 256] * W + bias.  CTA 128m x 128n, 8 warps (32m x 64n).
// smem 96KB: A 3-buf 16K @ (c%3)*16384; B 3-buf 16K @ 49152+(c%3)*16384.
// ONE __syncthreads per K-chunk; staging targets buffers retired >=1 barrier ago.
template<bool AHALF, bool CHALF>
__device__ __forceinline__ void gemm_uni(char* smem, int bx, int by,
                                         const void* Ap, const __half* __restrict__ Wf,
                                         const float* __restrict__ bias, void* Cp, int N)
{
    const int tid  = threadIdx.x;
    const int wid  = tid >> 5, lane = tid & 31;
    const int g    = lane >> 2, t = lane & 3;
    const int quad = lane >> 3, r8 = lane & 7;
    const int warp_m = wid & 3, warp_n = wid >> 2;
    const int m0 = by * 128, n0 = bx * 128;
    const int NTI = N >> 7;
    const uint32_t sbase = smem_u32(smem);

    auto issue_a = [&](int cc) {            // AHALF only: swizzled cp.async
        const char* src = (const char*)Ap + (size_t)m0 * 512 + cc * 128;
        const uint32_t d = sbase + (cc % 3) * 16384;
#pragma unroll
        for (int j = 0; j < 4; j++) {
            int idx = tid + j * 256;
            int r = idx >> 3, blk = idx & 7;
            cp16(d + SWZ((unsigned)(r * 128 + blk * 16)),
                 src + (size_t)r * 512 + blk * 16);
        }
    };
    auto issue_b = [&](int cc) {
        const char* src = (const char*)(Wf + (size_t)(cc * NTI + bx) * 8192);
        const uint32_t d = sbase + 49152 + (cc % 3) * 16384;
#pragma unroll
        for (int j = 0; j < 4; j++) {
            const int o = (tid + j * 256) * 16;
            cp16(d + o, src + o);
        }
    };

    const int a_r  = tid >> 4;
    const int a_c4 = (tid & 15) * 4;
    float4 av[8];
    auto load_a = [&](int cc) {             // fp32 path
#pragma unroll
        for (int i = 0; i < 8; i++) {
            int r = a_r + i * 16;
            av[i] = *(const float4*)((const float*)Ap + (size_t)(m0 + r) * 256 + cc * 64 + a_c4);
        }
    };
    auto store_a = [&](int cc) {
        char* bufp = smem + (cc % 3) * 16384;
#pragma unroll
        for (int i = 0; i < 8; i++) {
            int r = a_r + i * 16;
            unsigned off = SWZ((unsigned)(r * 128 + a_c4 * 2));
            *(uint2*)(bufp + off) = make_uint2(cvtf16(av[i].x, av[i].y),
                                               cvtf16(av[i].z, av[i].w));
        }
    };

    float acc[2][8][4];
#pragma unroll
    for (int i = 0; i < 2; i++)
#pragma unroll
        for (int j = 0; j < 8; j++)
#pragma unroll
            for (int r = 0; r < 4; r++) acc[i][j][r] = 0.f;

    if (AHALF) {
        issue_a(0); issue_b(0); cp_commit();
        issue_a(1); issue_b(1); cp_commit();
    } else {
        issue_b(0); cp_commit();
        issue_b(1); cp_commit();
        load_a(0); store_a(0);
    }
    cp_wait(1);
    __syncthreads();

    for (int c = 0; c < 4; c++) {
        if (!AHALF && c < 3) load_a(c + 1);

        const uint32_t sa = sbase + (c % 3) * 16384;
        const uint32_t sb = sbase + 49152 + (c % 3) * 16384;
#pragma unroll
        for (int kq = 0; kq < 4; kq++) {
            uint32_t ah[2][4];
#pragma unroll
            for (int mt = 0; mt < 2; mt++) {
                const int row = warp_m * 32 + mt * 16 + (quad & 1) * 8 + r8;
                const unsigned off = SWZ((unsigned)(row * 128 + kq * 32 + (quad >> 1) * 16));
                ldsm4(ah[mt], sa + off);
            }
#pragma unroll
            for (int nt2 = 0; nt2 < 4; nt2++) {
                const int brow = warp_n * 64 + nt2 * 16 + (quad >> 1) * 8 + r8;
                const unsigned boff = SWZ((unsigned)(brow * 128 + kq * 32 + (quad & 1) * 16));
                uint32_t bh[4];
                ldsm4(bh, sb + boff);
#pragma unroll
                for (int half = 0; half < 2; half++) {
#pragma unroll
                    for (int mt = 0; mt < 2; mt++) {
                        mma_f16(acc[mt][nt2 * 2 + half], ah[mt], bh + half * 2);
                    }
                }
            }
        }

        if (c < 3) {
            if (!AHALF) store_a(c + 1);
            if (c + 2 < 4) {
                if (AHALF) issue_a(c + 2);
                issue_b(c + 2);
                cp_commit();
            }
            cp_wait((c + 2 < 4) ? 1 : 0);
            __syncthreads();
        }
    }

#pragma unroll
    for (int mt = 0; mt < 2; mt++) {
#pragma unroll
        for (int nt = 0; nt < 8; nt++) {
            const int row = m0 + warp_m * 32 + mt * 16 + g;
            const int col = n0 + warp_n * 64 + nt * 8 + 2 * t;
            float2 bi = *(const float2*)&bias[col];
            float o0 = acc[mt][nt][0] + bi.x, o1 = acc[mt][nt][1] + bi.y;
            float o2 = acc[mt][nt][2] + bi.x, o3 = acc[mt][nt][3] + bi.y;
            if (CHALF) {
                __half* C = (__half*)Cp;
                *(__half2*)&C[(size_t)row * N + col]       = __floats2half2_rn(o0, o1);
                *(__half2*)&C[(size_t)(row + 8) * N + col] = __floats2half2_rn(o2, o3);
            } else {
                float* C = (float*)Cp;
                *(float2*)&C[(size_t)row * N + col]       = make_float2(o0, o1);
                *(float2*)&C[(size_t)(row + 8) * N + col] = make_float2(o2, o3);
            }
        }
    }
}

// ---------------- merged kernel: value proj + oa proj ------------------------
__global__ __launch_bounds__(256, 2)
void mega_gemm(const float* __restrict__ value, const __half* __restrict__ Wvf,
               const float* __restrict__ b_value, __half* __restrict__ Cv,
               const float* __restrict__ query, const __half* __restrict__ Woaf,
               const float* __restrict__ bias_oa, float* __restrict__ Coa)
{
    extern __shared__ __align__(1024) char smem[];
    const int bid = blockIdx.x;
    if (bid < 2720) {
        gemm_uni<false, true>(smem, bid & 1, bid >> 1, value, Wvf, b_value, Cv, 256);
    } else {
        const int t2 = bid - 2720;
        gemm_uni<false, false>(smem, t2 % 3, t2 / 3, query, Woaf, bias_oa, Coa, 384);
    }
}

// ---------------- out projection: fp16 A (g_acc) via cp.async ---------------
__global__ __launch_bounds__(256, 2)
void out_gemm(const __half* __restrict__ A, const __half* __restrict__ Wuf,
              const float* __restrict__ bias, float* __restrict__ C)
{
    extern __shared__ __align__(1024) char smem[];
    const int bid = blockIdx.x;
    gemm_uni<true, false>(smem, bid & 1, bid >> 1, A, Wuf, bias, C, 256);
}

// ---------------- fused softmax + bilinear sampling (2 queries per block) ---
// Phase B: lanes 0-15 handle point j, lanes 16-31 point j+1; each lane loads a
// __half2 channel pair -> one wavefront carries 2 points (128B vs 64B).
__global__ __launch_bounds__(256, 8)
void msda_sample2(const float* __restrict__ refer_bbox)
{
    __shared__ int   s_idx[256][4];
    __shared__ float s_w[256][4];

    const int bq0 = blockIdx.x * 2;
    const int tid = threadIdx.x;

    {
        const int task = tid >> 4;           // 0..15 = (q, h)
        const int q    = task >> 3;
        const int h    = task & 7;
        const int sub  = tid & 15;
        const int lvl  = sub >> 2;
        const int p    = sub & 3;
        const int bq   = bq0 + q;
        const int b    = bq >> 11;

        const float* qrow = g_offattn + (size_t)bq * 384;

        float logit = qrow[256 + h * 16 + sub];
        float mx = logit;
#pragma unroll
        for (int o = 8; o >= 1; o >>= 1)
            mx = fmaxf(mx, __shfl_xor_sync(0xffffffffu, mx, o));
        float e = expf(logit - mx);
        float sm = e;
#pragma unroll
        for (int o = 8; o >= 1; o >>= 1)
            sm += __shfl_xor_sync(0xffffffffu, sm, o);
        const float aw = e / sm;

        const int Hh = c_H[lvl], Ww = c_W[lvl], st = c_start[lvl];
        const float rx = refer_bbox[(size_t)bq * 8 + lvl * 2 + 0];
        const float ry = refer_bbox[(size_t)bq * 8 + lvl * 2 + 1];
        const float ox = qrow[h * 32 + lvl * 8 + p * 2 + 0];
        const float oy = qrow[h * 32 + lvl * 8 + p * 2 + 1];

        const float x = (rx + ox / (float)Ww) * (float)Ww - 0.5f;
        const float y = (ry + oy / (float)Hh) * (float)Hh - 0.5f;
        const float x0f = floorf(x), y0f = floorf(y);
        const float fx = x - x0f, fy = y - y0f;
        const int x0 = (int)x0f, y0 = (int)y0f;
        const int x1 = x0 + 1,   y1 = y0 + 1;

        const bool vx0 = (x0 >= 0) & (x0 < Ww);
        const bool vx1 = (x1 >= 0) & (x1 < Ww);
        const bool vy0 = (y0 >= 0) & (y0 < Hh);
        const bool vy1 = (y1 >= 0) & (y1 < Hh);

        float w00 = (1.f - fx) * (1.f - fy); if (!(vx0 && vy0)) w00 = 0.f;
        float w10 = fx         * (1.f - fy); if (!(vx1 && vy0)) w10 = 0.f;
        float w01 = (1.f - fx) * fy;         if (!(vx0 && vy1)) w01 = 0.f;
        float w11 = fx         * fy;         if (!(vx1 && vy1)) w11 = 0.f;

        const int cx0 = min(max(x0, 0), Ww - 1);
        const int cx1 = min(max(x1, 0), Ww - 1);
        const int cy0 = min(max(y0, 0), Hh - 1);
        const int cy1 = min(max(y1, 0), Hh - 1);

        const int base = (b * LVTOT + st) * DMODEL + h * 32;
        s_idx[tid][0] = base + (cy0 * Ww + cx0) * DMODEL;
        s_idx[tid][1] = base + (cy0 * Ww + cx1) * DMODEL;
        s_idx[tid][2] = base + (cy1 * Ww + cx0) * DMODEL;
        s_idx[tid][3] = base + (cy1 * Ww + cx1) * DMODEL;
        s_w[tid][0] = w00 * aw;
        s_w[tid][1] = w10 * aw;
        s_w[tid][2] = w01 * aw;
        s_w[tid][3] = w11 * aw;
    }
    __syncthreads();

    const int h  = tid >> 5, lane = tid & 31;
    const int pp = lane >> 4;            // point parity
    const int c2 = (lane & 15) * 2;      // channel offset (halves)
#pragma unroll
    for (int q = 0; q < 2; q++) {
        float ax = 0.f, ay = 0.f;
        const int base = q * 128 + h * 16;
#pragma unroll
        for (int j = 0; j < 16; j += 2) {
            const int4   id = *(const int4*)  s_idx[base + j + pp];
            const float4 w  = *(const float4*)s_w  [base + j + pp];
            float2 v0 = __half22float2(*(const __half2*)&g_v[id.x + c2]);
            float2 v1 = __half22float2(*(const __half2*)&g_v[id.y + c2]);
            float2 v2 = __half22float2(*(const __half2*)&g_v[id.z + c2]);
            float2 v3 = __half22float2(*(const __half2*)&g_v[id.w + c2]);
            ax = fmaf(w.x, v0.x, fmaf(w.y, v1.x, fmaf(w.z, v2.x, fmaf(w.w, v3.x, ax))));
            ay = fmaf(w.x, v0.y, fmaf(w.y, v1.y, fmaf(w.z, v2.y, fmaf(w.w, v3.y, ay))));
        }
        ax += __shfl_xor_sync(0xffffffffu, ax, 16);
        ay += __shfl_xor_sync(0xffffffffu, ay, 16);
        if (pp == 0)
            *(__half2*)&g_acc[(size_t)(bq0 + q) * DMODEL + h * 32 + c2] =
                __floats2half2_rn(ax, ay);
    }
}

// ---------------- launch -----------------------------------------------
extern "C" void kernel_launch(void* const* d_in, const int* in_sizes, int n_in,
                              void* d_out, int out_size)
{
    const float* query   = (const float*)d_in[0];
    const float* rbbox   = (const float*)d_in[1];
    const float* value   = (const float*)d_in[2];
    const float* W_value = (const float*)d_in[4];
    const float* b_value = (const float*)d_in[5];
    const float* W_off   = (const float*)d_in[6];
    const float* b_off   = (const float*)d_in[7];
    const float* W_attn  = (const float*)d_in[8];
    const float* b_attn  = (const float*)d_in[9];
    const float* W_out   = (const float*)d_in[10];
    const float* b_out   = (const float*)d_in[11];
    float* out = (float*)d_out;

    __half *pv, *pacc;
    float *poa, *pboa;
    cudaGetSymbolAddress((void**)&pv,   g_v);
    cudaGetSymbolAddress((void**)&poa,  g_offattn);
    cudaGetSymbolAddress((void**)&pacc, g_acc);
    cudaGetSymbolAddress((void**)&pboa, g_bias_oa);

    __half *wvf, *woaf, *wuf;
    cudaGetSymbolAddress((void**)&wvf,  g_Wvf);
    cudaGetSymbolAddress((void**)&woaf, g_Woaf);
    cudaGetSymbolAddress((void**)&wuf,  g_Wuf);

    static bool attr_done = false;
    if (!attr_done) {
        cudaFuncSetAttribute(mega_gemm, cudaFuncAttributeMaxDynamicSharedMemorySize, 98304);
        cudaFuncSetAttribute(out_gemm,  cudaFuncAttributeMaxDynamicSharedMemorySize, 98304);
        attr_done = true;
    }
    const int SMEM = 98304;

    // 0) all weight prep in one launch
    prep_all<<<640, 256>>>(W_value, W_off, W_attn, W_out, b_off, b_attn);

    // 1) merged: value projection (blocks 0..2719) + off/attn (2720..3103)
    mega_gemm<<<3104, 256, SMEM>>>(value, wvf, b_value, pv,
                                   query, woaf, pboa, poa);
    // 2) softmax + sampling (2 queries per block, paired-point loads)
    msda_sample2<<<BS * QLEN / 2, 256>>>(rbbox);
    // 3) output projection (fp16 A via cp.async)
    out_gemm<<<256, 256, SMEM>>>(pacc, wuf, b_out, out);
}